// round 1
// baseline (speedup 1.0000x reference)
#include <cuda_runtime.h>
#include <math.h>

#define SEQ    2048
#define DMODEL 2048
#define NH     32
#define NKV    8
#define HD     64
#define KVD    (NKV*HD)   // 512

// -------------------- scratch (no allocs allowed) --------------------
__device__ float g_q[SEQ*DMODEL];
__device__ float g_k[SEQ*KVD];
__device__ float g_v[SEQ*KVD];
__device__ float g_ctx[SEQ*DMODEL];
__device__ float g_cos[SEQ*(HD/2)];
__device__ float g_sin[SEQ*(HD/2)];

// -------------------- RoPE tables (llama3 freq scaling) --------------------
__global__ void rope_table_kernel(const int* __restrict__ start_pos) {
    int idx = blockIdx.x * blockDim.x + threadIdx.x;
    if (idx >= SEQ * 32) return;
    int t = idx >> 5, j = idx & 31;
    const double PI = 3.14159265358979323846;
    double e = (double)(2 * j) / 64.0;
    double invf = pow(500000.0, -e);
    double wavelen = 2.0 * PI / invf;
    double inv;
    if (wavelen > 8192.0) {
        inv = invf / 32.0;
    } else if (wavelen < 2048.0) {
        inv = invf;
    } else {
        double smooth = (8192.0 / wavelen - 1.0) / 3.0;
        inv = (1.0 - smooth) * (invf / 32.0) + smooth * invf;
    }
    // match reference: angle formed & rounded in fp32, trig evaluated precisely
    float angle = (float)(start_pos[0] + t) * (float)inv;
    g_cos[idx] = (float)cos((double)angle);
    g_sin[idx] = (float)sin((double)angle);
}

__global__ void rope_apply_kernel(float* __restrict__ buf, int n_heads) {
    int idx = blockIdx.x * blockDim.x + threadIdx.x;
    int total = SEQ * n_heads * 32;
    if (idx >= total) return;
    int j = idx & 31;
    int h = (idx >> 5) % n_heads;
    int t = idx / (32 * n_heads);
    float c = g_cos[t * 32 + j];
    float s = g_sin[t * 32 + j];
    float* p = buf + (size_t)t * n_heads * 64 + h * 64 + j;
    float x1 = p[0], x2 = p[32];
    p[0]  = x1 * c - x2 * s;
    p[32] = x2 * c + x1 * s;
}

// -------------------- fp32 SGEMM: C[M,N] = A[M,K] @ B[N,K]^T --------------------
// 128x128 block tile, BK=16, 256 threads, 8x8 micro-tile.
#define BM 128
#define BN 128
#define BK 16
#define ASTR 132   // padded smem stride (floats)

__global__ void __launch_bounds__(256) sgemm_nt(const float* __restrict__ A,
                                                const float* __restrict__ B,
                                                float* __restrict__ C,
                                                int M, int N, int K) {
    __shared__ float As[BK][ASTR];
    __shared__ float Bs[BK][ASTR];
    int bm = blockIdx.y * BM;
    int bn = blockIdx.x * BN;
    int tid = threadIdx.x;
    int tx = tid & 15;    // 0..15 -> N micro
    int ty = tid >> 4;    // 0..15 -> M micro
    float acc[8][8];
#pragma unroll
    for (int i = 0; i < 8; i++)
#pragma unroll
        for (int j = 0; j < 8; j++) acc[i][j] = 0.f;

    for (int k0 = 0; k0 < K; k0 += BK) {
#pragma unroll
        for (int l = 0; l < 2; l++) {
            int i = tid + l * 256;      // float4 index 0..511
            int m = i >> 2;             // 0..127
            int kk = (i & 3) * 4;       // 0,4,8,12
            float4 a = *(const float4*)(A + (size_t)(bm + m) * K + k0 + kk);
            As[kk + 0][m] = a.x; As[kk + 1][m] = a.y;
            As[kk + 2][m] = a.z; As[kk + 3][m] = a.w;
            float4 b = *(const float4*)(B + (size_t)(bn + m) * K + k0 + kk);
            Bs[kk + 0][m] = b.x; Bs[kk + 1][m] = b.y;
            Bs[kk + 2][m] = b.z; Bs[kk + 3][m] = b.w;
        }
        __syncthreads();
#pragma unroll
        for (int k = 0; k < BK; k++) {
            float4 a0 = *(const float4*)&As[k][ty * 4];
            float4 a1 = *(const float4*)&As[k][64 + ty * 4];
            float4 b0 = *(const float4*)&Bs[k][tx * 4];
            float4 b1 = *(const float4*)&Bs[k][64 + tx * 4];
            float ar[8] = {a0.x, a0.y, a0.z, a0.w, a1.x, a1.y, a1.z, a1.w};
            float br[8] = {b0.x, b0.y, b0.z, b0.w, b1.x, b1.y, b1.z, b1.w};
#pragma unroll
            for (int i = 0; i < 8; i++)
#pragma unroll
                for (int j = 0; j < 8; j++) acc[i][j] += ar[i] * br[j];
        }
        __syncthreads();
    }
#pragma unroll
    for (int i = 0; i < 8; i++) {
        int row = bm + ((i < 4) ? (ty * 4 + i) : (64 + ty * 4 + i - 4));
        float4 v0 = make_float4(acc[i][0], acc[i][1], acc[i][2], acc[i][3]);
        float4 v1 = make_float4(acc[i][4], acc[i][5], acc[i][6], acc[i][7]);
        *(float4*)(C + (size_t)row * N + bn + tx * 4) = v0;
        *(float4*)(C + (size_t)row * N + bn + 64 + tx * 4) = v1;
    }
}

// -------------------- flash attention (causal, GQA) --------------------
// 64x64 tiles, hd=64, 256 threads, 4x4 micro-tiles, online softmax.
#define KS 65
#define FLASH_SMEM_BYTES (4 * 64 * KS * (int)sizeof(float))

__global__ void __launch_bounds__(256) flash_kernel(const float* __restrict__ q,
                                                    const float* __restrict__ k,
                                                    const float* __restrict__ v,
                                                    float* __restrict__ ctx) {
    extern __shared__ float sm[];
    float* Qs  = sm;                 // 64 x KS
    float* Ksm = Qs  + 64 * KS;
    float* Vsm = Ksm + 64 * KS;
    float* Ps  = Vsm + 64 * KS;

    int h  = blockIdx.y;             // 0..31
    int qb = blockIdx.x;             // 0..31
    int g  = h >> 2;                 // kv head
    int tid = threadIdx.x;
    int rg = tid >> 4, cg = tid & 15;
    int r0 = rg * 4, c0 = cg * 4;

    // load Q tile once (64 rows x 64 dims)
#pragma unroll
    for (int l = 0; l < 4; l++) {
        int i = tid + l * 256;       // float4 idx 0..1023
        int r = i >> 4;
        int d = (i & 15) * 4;
        float4 t4 = *(const float4*)(q + (size_t)(qb * 64 + r) * DMODEL + h * 64 + d);
        Qs[r * KS + d]     = t4.x;
        Qs[r * KS + d + 1] = t4.y;
        Qs[r * KS + d + 2] = t4.z;
        Qs[r * KS + d + 3] = t4.w;
    }

    float o[4][4];
    float mi[4], li[4];
#pragma unroll
    for (int i = 0; i < 4; i++) {
        mi[i] = -INFINITY; li[i] = 0.f;
#pragma unroll
        for (int j = 0; j < 4; j++) o[i][j] = 0.f;
    }

    for (int kb = 0; kb <= qb; kb++) {
        __syncthreads();   // protect Ks/Vs/Ps from previous iteration's readers
#pragma unroll
        for (int l = 0; l < 4; l++) {
            int i = tid + l * 256;
            int r = i >> 4;
            int d = (i & 15) * 4;
            float4 t4 = *(const float4*)(k + (size_t)(kb * 64 + r) * KVD + g * 64 + d);
            Ksm[r * KS + d]     = t4.x;
            Ksm[r * KS + d + 1] = t4.y;
            Ksm[r * KS + d + 2] = t4.z;
            Ksm[r * KS + d + 3] = t4.w;
            float4 u4 = *(const float4*)(v + (size_t)(kb * 64 + r) * KVD + g * 64 + d);
            Vsm[r * KS + d]     = u4.x;
            Vsm[r * KS + d + 1] = u4.y;
            Vsm[r * KS + d + 2] = u4.z;
            Vsm[r * KS + d + 3] = u4.w;
        }
        __syncthreads();

        // S = Q K^T (this thread: rows r0..r0+3, cols c0..c0+3)
        float s[4][4];
#pragma unroll
        for (int i = 0; i < 4; i++)
#pragma unroll
            for (int j = 0; j < 4; j++) s[i][j] = 0.f;
#pragma unroll 4
        for (int d = 0; d < 64; d++) {
            float qv[4], kv[4];
#pragma unroll
            for (int i = 0; i < 4; i++) qv[i] = Qs[(r0 + i) * KS + d];
#pragma unroll
            for (int j = 0; j < 4; j++) kv[j] = Ksm[(c0 + j) * KS + d];
#pragma unroll
            for (int i = 0; i < 4; i++)
#pragma unroll
                for (int j = 0; j < 4; j++) s[i][j] += qv[i] * kv[j];
        }

        // scale + causal mask (mask then scale matches ref: -inf/8 = -inf)
        if (kb == qb) {
#pragma unroll
            for (int i = 0; i < 4; i++)
#pragma unroll
                for (int j = 0; j < 4; j++)
                    s[i][j] = (c0 + j <= r0 + i) ? s[i][j] * 0.125f : -INFINITY;
        } else {
#pragma unroll
            for (int i = 0; i < 4; i++)
#pragma unroll
                for (int j = 0; j < 4; j++) s[i][j] *= 0.125f;
        }

        // online softmax (row groups = 16 lanes within a warp half)
#pragma unroll
        for (int i = 0; i < 4; i++) {
            float mx = fmaxf(fmaxf(s[i][0], s[i][1]), fmaxf(s[i][2], s[i][3]));
#pragma unroll
            for (int off = 1; off < 16; off <<= 1)
                mx = fmaxf(mx, __shfl_xor_sync(0xffffffffu, mx, off));
            float mnew = fmaxf(mi[i], mx);
            float sum = 0.f;
#pragma unroll
            for (int j = 0; j < 4; j++) {
                float p = __expf(s[i][j] - mnew);
                s[i][j] = p;
                sum += p;
            }
#pragma unroll
            for (int off = 1; off < 16; off <<= 1)
                sum += __shfl_xor_sync(0xffffffffu, sum, off);
            float sc = __expf(mi[i] - mnew);
            li[i] = li[i] * sc + sum;
            mi[i] = mnew;
#pragma unroll
            for (int j = 0; j < 4; j++) o[i][j] *= sc;
        }

        // stage P to smem, then O += P @ V
#pragma unroll
        for (int i = 0; i < 4; i++)
#pragma unroll
            for (int j = 0; j < 4; j++) Ps[(r0 + i) * KS + c0 + j] = s[i][j];
        __syncthreads();
#pragma unroll 4
        for (int kk = 0; kk < 64; kk++) {
            float pv[4], vv[4];
#pragma unroll
            for (int i = 0; i < 4; i++) pv[i] = Ps[(r0 + i) * KS + kk];
#pragma unroll
            for (int j = 0; j < 4; j++) vv[j] = Vsm[kk * KS + c0 + j];
#pragma unroll
            for (int i = 0; i < 4; i++)
#pragma unroll
                for (int j = 0; j < 4; j++) o[i][j] += pv[i] * vv[j];
        }
    }

#pragma unroll
    for (int i = 0; i < 4; i++) {
        float inv = 1.0f / li[i];
#pragma unroll
        for (int j = 0; j < 4; j++)
            ctx[(size_t)(qb * 64 + r0 + i) * DMODEL + h * 64 + c0 + j] = o[i][j] * inv;
    }
}

// -------------------- launch --------------------
extern "C" void kernel_launch(void* const* d_in, const int* in_sizes, int n_in,
                              void* d_out, int out_size) {
    const float* x  = (const float*)d_in[0];
    const float* Wq = (const float*)d_in[1];
    const float* Wk = (const float*)d_in[2];
    const float* Wv = (const float*)d_in[3];
    const float* Wo = (const float*)d_in[4];
    const int* start_pos = (const int*)d_in[5];
    float* out = (float*)d_out;

    float *qp, *kp, *vp, *cp;
    cudaGetSymbolAddress((void**)&qp, g_q);
    cudaGetSymbolAddress((void**)&kp, g_k);
    cudaGetSymbolAddress((void**)&vp, g_v);
    cudaGetSymbolAddress((void**)&cp, g_ctx);

    rope_table_kernel<<<(SEQ * 32 + 255) / 256, 256>>>(start_pos);

    sgemm_nt<<<dim3(DMODEL / BN, SEQ / BM), 256>>>(x, Wq, qp, SEQ, DMODEL, DMODEL);
    sgemm_nt<<<dim3(KVD / BN,    SEQ / BM), 256>>>(x, Wk, kp, SEQ, KVD, DMODEL);
    sgemm_nt<<<dim3(KVD / BN,    SEQ / BM), 256>>>(x, Wv, vp, SEQ, KVD, DMODEL);

    rope_apply_kernel<<<(SEQ * NH  * 32 + 255) / 256, 256>>>(qp, NH);
    rope_apply_kernel<<<(SEQ * NKV * 32 + 255) / 256, 256>>>(kp, NKV);

    cudaFuncSetAttribute(flash_kernel, cudaFuncAttributeMaxDynamicSharedMemorySize,
                         FLASH_SMEM_BYTES);
    flash_kernel<<<dim3(SEQ / 64, NH), 256, FLASH_SMEM_BYTES>>>(qp, kp, vp, cp);

    sgemm_nt<<<dim3(DMODEL / BN, SEQ / BM), 256>>>(cp, Wo, out, SEQ, DMODEL, DMODEL);
}

// round 3
// speedup vs baseline: 1.4906x; 1.4906x over previous
#include <cuda_runtime.h>
#include <cuda_fp16.h>
#include <math.h>
#include <stdint.h>

#define SEQ    2048
#define DMODEL 2048
#define NH     32
#define NKV    8
#define HD     64
#define KVD    (NKV*HD)   // 512

// -------------------- scratch (no allocs allowed) --------------------
__device__ float g_q[SEQ*DMODEL];
__device__ float g_k[SEQ*KVD];
__device__ float g_v[SEQ*KVD];
__device__ float g_ctx[SEQ*DMODEL];
__device__ float g_cos[SEQ*(HD/2)];
__device__ float g_sin[SEQ*(HD/2)];

// fp16 split buffers (hi/lo)
__device__ __half g_xhi[SEQ*DMODEL],     g_xlo[SEQ*DMODEL];
__device__ __half g_wqhi[DMODEL*DMODEL], g_wqlo[DMODEL*DMODEL];
__device__ __half g_wkhi[KVD*DMODEL],    g_wklo[KVD*DMODEL];
__device__ __half g_wvhi[KVD*DMODEL],    g_wvlo[KVD*DMODEL];
__device__ __half g_wohi[DMODEL*DMODEL], g_wolo[DMODEL*DMODEL];
__device__ __half g_chi[SEQ*DMODEL],     g_clo[SEQ*DMODEL];

// ==================== helpers ====================
__device__ __forceinline__ uint32_t smem_u32(const void* p) {
    uint32_t a;
    asm("{ .reg .u64 t; cvta.to.shared.u64 t, %1; cvt.u32.u64 %0, t; }"
        : "=r"(a) : "l"(p));
    return a;
}

#define CP_ASYNC16(dst, src) \
    asm volatile("cp.async.cg.shared.global [%0], [%1], 16;" :: "r"(dst), "l"(src) : "memory")
#define CP_COMMIT() asm volatile("cp.async.commit_group;" ::: "memory")
#define CP_WAIT_1() asm volatile("cp.async.wait_group 1;" ::: "memory")
#define CP_WAIT_0() asm volatile("cp.async.wait_group 0;" ::: "memory")

#define LDSM4(r0, r1, r2, r3, addr) \
    asm volatile("ldmatrix.sync.aligned.m8n8.x4.shared.b16 {%0,%1,%2,%3}, [%4];" \
        : "=r"(r0), "=r"(r1), "=r"(r2), "=r"(r3) : "r"(addr))

#define MMA16816(d, a, b0, b1) \
    asm volatile("mma.sync.aligned.m16n8k16.row.col.f32.f16.f16.f32 " \
        "{%0,%1,%2,%3}, {%4,%5,%6,%7}, {%8,%9}, {%0,%1,%2,%3};" \
        : "+f"((d)[0]), "+f"((d)[1]), "+f"((d)[2]), "+f"((d)[3]) \
        : "r"((a)[0]), "r"((a)[1]), "r"((a)[2]), "r"((a)[3]), "r"(b0), "r"(b1))

// ==================== fp32 -> fp16 hi/lo split ====================
__global__ void split_kernel(const float* __restrict__ src,
                             __half* __restrict__ hi,
                             __half* __restrict__ lo, int n4) {
    int i = blockIdx.x * blockDim.x + threadIdx.x;
    if (i >= n4) return;
    float4 x = ((const float4*)src)[i];
    __half h0 = __float2half_rn(x.x), h1 = __float2half_rn(x.y);
    __half h2 = __float2half_rn(x.z), h3 = __float2half_rn(x.w);
    __half2* hp = (__half2*)(hi + i * 4);
    __half2* lp = (__half2*)(lo + i * 4);
    hp[0] = __half2(h0, h1);
    hp[1] = __half2(h2, h3);
    lp[0] = __half2(__float2half_rn(x.x - __half2float(h0)),
                    __float2half_rn(x.y - __half2float(h1)));
    lp[1] = __half2(__float2half_rn(x.z - __half2float(h2)),
                    __float2half_rn(x.w - __half2float(h3)));
}

// ==================== HMMA fp16x3 GEMM ====================
// C[M,N] = A[M,K] @ B[N,K]^T via 3 K-segments: AhiBhi + AhiBlo + AloBhi
// CTA tile 128x128, BK=32, 8 warps (2x4), warp tile 64x32, cp.async 2-stage.
#define BM 128
#define BN 128
#define BK 32
#define ASTRH 40   // padded halves per smem row (80B) -> conflict-free ldmatrix

__global__ void __launch_bounds__(256) gemm_hmma(
    const __half* __restrict__ Ahi, const __half* __restrict__ Alo,
    const __half* __restrict__ Bhi0, const __half* __restrict__ Blo0,
    const __half* __restrict__ Bhi1, const __half* __restrict__ Blo1,
    float* __restrict__ C0, float* __restrict__ C1,
    int M, int N, int K) {
    __shared__ __half sA[2][BM * ASTRH];
    __shared__ __half sB[2][BN * ASTRH];

    const __half* Bhi = blockIdx.z ? Bhi1 : Bhi0;
    const __half* Blo = blockIdx.z ? Blo1 : Blo0;
    float* C = blockIdx.z ? C1 : C0;

    const int tid = threadIdx.x;
    const int wid = tid >> 5, lane = tid & 31;
    const int wm = (wid & 1) * 64;      // warp row offset
    const int wn = (wid >> 1) * 32;     // warp col offset
    const int bm = blockIdx.y * BM, bn = blockIdx.x * BN;

    const __half* Asrc[3] = {Ahi, Ahi, Alo};
    const __half* Bsrc[3] = {Bhi, Blo, Bhi};

    const int kiters = K / BK;
    const int NIT = 3 * kiters;

    // per-thread load chunk coords (2 chunks per tile, A and B)
    const int row0 = tid >> 2, part0 = (tid & 3);          // chunk 0: rows 0..63
    const int row1 = (tid + 256) >> 2, part1 = (tid & 3);  // chunk 1: rows 64..127

    uint32_t sAu = smem_u32(sA), sBu = smem_u32(sB);
    const uint32_t stageBytes = BM * ASTRH * 2;

    float acc[4][4][4];
#pragma unroll
    for (int a = 0; a < 4; a++)
#pragma unroll
        for (int b = 0; b < 4; b++)
#pragma unroll
            for (int c = 0; c < 4; c++) acc[a][b][c] = 0.f;

#define LOAD_TILES(stage, it) do {                                             \
    int _seg = (it) / kiters; int _k0 = ((it) % kiters) * BK;                  \
    const __half* _A = Asrc[_seg]; const __half* _B = Bsrc[_seg];              \
    uint32_t _sa = sAu + (stage) * stageBytes;                                 \
    uint32_t _sb = sBu + (stage) * stageBytes;                                 \
    CP_ASYNC16(_sa + (row0 * ASTRH + part0 * 8) * 2,                           \
               _A + (size_t)(bm + row0) * K + _k0 + part0 * 8);                \
    CP_ASYNC16(_sa + (row1 * ASTRH + part1 * 8) * 2,                           \
               _A + (size_t)(bm + row1) * K + _k0 + part1 * 8);                \
    CP_ASYNC16(_sb + (row0 * ASTRH + part0 * 8) * 2,                           \
               _B + (size_t)(bn + row0) * K + _k0 + part0 * 8);                \
    CP_ASYNC16(_sb + (row1 * ASTRH + part1 * 8) * 2,                           \
               _B + (size_t)(bn + row1) * K + _k0 + part1 * 8);                \
} while (0)

    LOAD_TILES(0, 0);
    CP_COMMIT();

    for (int it = 0; it < NIT; it++) {
        int stage = it & 1;
        if (it + 1 < NIT) {
            LOAD_TILES(stage ^ 1, it + 1);
            CP_COMMIT();
            CP_WAIT_1();
        } else {
            CP_WAIT_0();
        }
        __syncthreads();

        uint32_t sa = sAu + stage * stageBytes;
        uint32_t sb = sBu + stage * stageBytes;
        int lr = lane & 15, lc = lane >> 4;   // ldmatrix lane mapping

#pragma unroll
        for (int k16 = 0; k16 < 2; k16++) {
            uint32_t a[4][4];
#pragma unroll
            for (int mt = 0; mt < 4; mt++) {
                uint32_t addr = sa + ((wm + mt * 16 + lr) * ASTRH
                                      + k16 * 16 + lc * 8) * 2;
                LDSM4(a[mt][0], a[mt][1], a[mt][2], a[mt][3], addr);
            }
            uint32_t b[2][4];
#pragma unroll
            for (int p = 0; p < 2; p++) {
                uint32_t addr = sb + ((wn + p * 16 + lr) * ASTRH
                                      + k16 * 16 + lc * 8) * 2;
                LDSM4(b[p][0], b[p][1], b[p][2], b[p][3], addr);
            }
#pragma unroll
            for (int mt = 0; mt < 4; mt++)
#pragma unroll
                for (int nt = 0; nt < 4; nt++) {
                    int p = nt >> 1, w = nt & 1;
                    MMA16816(acc[mt][nt], a[mt], b[p][w], b[p][w + 2]);
                }
        }
        __syncthreads();
    }

    // epilogue: fp32 direct to global
    int er = lane >> 2, ec = (lane & 3) * 2;
#pragma unroll
    for (int mt = 0; mt < 4; mt++) {
#pragma unroll
        for (int nt = 0; nt < 4; nt++) {
            int r = bm + wm + mt * 16 + er;
            int c = bn + wn + nt * 8 + ec;
            *(float2*)&C[(size_t)r * N + c]       = make_float2(acc[mt][nt][0], acc[mt][nt][1]);
            *(float2*)&C[(size_t)(r + 8) * N + c] = make_float2(acc[mt][nt][2], acc[mt][nt][3]);
        }
    }
}

// -------------------- RoPE tables (llama3 freq scaling) --------------------
__global__ void rope_table_kernel(const int* __restrict__ start_pos) {
    int idx = blockIdx.x * blockDim.x + threadIdx.x;
    if (idx >= SEQ * 32) return;
    int t = idx >> 5, j = idx & 31;
    const double PI = 3.14159265358979323846;
    double e = (double)(2 * j) / 64.0;
    double invf = pow(500000.0, -e);
    double wavelen = 2.0 * PI / invf;
    double inv;
    if (wavelen > 8192.0) {
        inv = invf / 32.0;
    } else if (wavelen < 2048.0) {
        inv = invf;
    } else {
        double smooth = (8192.0 / wavelen - 1.0) / 3.0;
        inv = (1.0 - smooth) * (invf / 32.0) + smooth * invf;
    }
    float angle = (float)(start_pos[0] + t) * (float)inv;
    g_cos[idx] = (float)cos((double)angle);
    g_sin[idx] = (float)sin((double)angle);
}

__global__ void rope_apply_kernel(float* __restrict__ buf, int n_heads) {
    int idx = blockIdx.x * blockDim.x + threadIdx.x;
    int total = SEQ * n_heads * 32;
    if (idx >= total) return;
    int j = idx & 31;
    int h = (idx >> 5) % n_heads;
    int t = idx / (32 * n_heads);
    float c = g_cos[t * 32 + j];
    float s = g_sin[t * 32 + j];
    float* p = buf + (size_t)t * n_heads * 64 + h * 64 + j;
    float x1 = p[0], x2 = p[32];
    p[0]  = x1 * c - x2 * s;
    p[32] = x2 * c + x1 * s;
}

// -------------------- flash attention (causal, GQA) --------------------
#define KS 65
#define FLASH_SMEM_BYTES (4 * 64 * KS * (int)sizeof(float))

__global__ void __launch_bounds__(256) flash_kernel(const float* __restrict__ q,
                                                    const float* __restrict__ k,
                                                    const float* __restrict__ v,
                                                    float* __restrict__ ctx) {
    extern __shared__ float sm[];
    float* Qs  = sm;
    float* Ksm = Qs  + 64 * KS;
    float* Vsm = Ksm + 64 * KS;
    float* Ps  = Vsm + 64 * KS;

    int h  = blockIdx.y;
    int qb = blockIdx.x;
    int g  = h >> 2;
    int tid = threadIdx.x;
    int rg = tid >> 4, cg = tid & 15;
    int r0 = rg * 4, c0 = cg * 4;

#pragma unroll
    for (int l = 0; l < 4; l++) {
        int i = tid + l * 256;
        int r = i >> 4;
        int d = (i & 15) * 4;
        float4 t4 = *(const float4*)(q + (size_t)(qb * 64 + r) * DMODEL + h * 64 + d);
        Qs[r * KS + d]     = t4.x;
        Qs[r * KS + d + 1] = t4.y;
        Qs[r * KS + d + 2] = t4.z;
        Qs[r * KS + d + 3] = t4.w;
    }

    float o[4][4];
    float mi[4], li[4];
#pragma unroll
    for (int i = 0; i < 4; i++) {
        mi[i] = -INFINITY; li[i] = 0.f;
#pragma unroll
        for (int j = 0; j < 4; j++) o[i][j] = 0.f;
    }

    for (int kb = 0; kb <= qb; kb++) {
        __syncthreads();
#pragma unroll
        for (int l = 0; l < 4; l++) {
            int i = tid + l * 256;
            int r = i >> 4;
            int d = (i & 15) * 4;
            float4 t4 = *(const float4*)(k + (size_t)(kb * 64 + r) * KVD + g * 64 + d);
            Ksm[r * KS + d]     = t4.x;
            Ksm[r * KS + d + 1] = t4.y;
            Ksm[r * KS + d + 2] = t4.z;
            Ksm[r * KS + d + 3] = t4.w;
            float4 u4 = *(const float4*)(v + (size_t)(kb * 64 + r) * KVD + g * 64 + d);
            Vsm[r * KS + d]     = u4.x;
            Vsm[r * KS + d + 1] = u4.y;
            Vsm[r * KS + d + 2] = u4.z;
            Vsm[r * KS + d + 3] = u4.w;
        }
        __syncthreads();

        float s[4][4];
#pragma unroll
        for (int i = 0; i < 4; i++)
#pragma unroll
            for (int j = 0; j < 4; j++) s[i][j] = 0.f;
#pragma unroll 4
        for (int d = 0; d < 64; d++) {
            float qv[4], kv[4];
#pragma unroll
            for (int i = 0; i < 4; i++) qv[i] = Qs[(r0 + i) * KS + d];
#pragma unroll
            for (int j = 0; j < 4; j++) kv[j] = Ksm[(c0 + j) * KS + d];
#pragma unroll
            for (int i = 0; i < 4; i++)
#pragma unroll
                for (int j = 0; j < 4; j++) s[i][j] += qv[i] * kv[j];
        }

        if (kb == qb) {
#pragma unroll
            for (int i = 0; i < 4; i++)
#pragma unroll
                for (int j = 0; j < 4; j++)
                    s[i][j] = (c0 + j <= r0 + i) ? s[i][j] * 0.125f : -INFINITY;
        } else {
#pragma unroll
            for (int i = 0; i < 4; i++)
#pragma unroll
                for (int j = 0; j < 4; j++) s[i][j] *= 0.125f;
        }

#pragma unroll
        for (int i = 0; i < 4; i++) {
            float mx = fmaxf(fmaxf(s[i][0], s[i][1]), fmaxf(s[i][2], s[i][3]));
#pragma unroll
            for (int off = 1; off < 16; off <<= 1)
                mx = fmaxf(mx, __shfl_xor_sync(0xffffffffu, mx, off));
            float mnew = fmaxf(mi[i], mx);
            float sum = 0.f;
#pragma unroll
            for (int j = 0; j < 4; j++) {
                float p = __expf(s[i][j] - mnew);
                s[i][j] = p;
                sum += p;
            }
#pragma unroll
            for (int off = 1; off < 16; off <<= 1)
                sum += __shfl_xor_sync(0xffffffffu, sum, off);
            float sc = __expf(mi[i] - mnew);
            li[i] = li[i] * sc + sum;
            mi[i] = mnew;
#pragma unroll
            for (int j = 0; j < 4; j++) o[i][j] *= sc;
        }

#pragma unroll
        for (int i = 0; i < 4; i++)
#pragma unroll
            for (int j = 0; j < 4; j++) Ps[(r0 + i) * KS + c0 + j] = s[i][j];
        __syncthreads();
#pragma unroll 4
        for (int kk = 0; kk < 64; kk++) {
            float pv[4], vv[4];
#pragma unroll
            for (int i = 0; i < 4; i++) pv[i] = Ps[(r0 + i) * KS + kk];
#pragma unroll
            for (int j = 0; j < 4; j++) vv[j] = Vsm[kk * KS + c0 + j];
#pragma unroll
            for (int i = 0; i < 4; i++)
#pragma unroll
                for (int j = 0; j < 4; j++) o[i][j] += pv[i] * vv[j];
        }
    }

#pragma unroll
    for (int i = 0; i < 4; i++) {
        float inv = 1.0f / li[i];
#pragma unroll
        for (int j = 0; j < 4; j++)
            ctx[(size_t)(qb * 64 + r0 + i) * DMODEL + h * 64 + c0 + j] = o[i][j] * inv;
    }
}

// -------------------- launch --------------------
extern "C" void kernel_launch(void* const* d_in, const int* in_sizes, int n_in,
                              void* d_out, int out_size) {
    const float* x  = (const float*)d_in[0];
    const float* Wq = (const float*)d_in[1];
    const float* Wk = (const float*)d_in[2];
    const float* Wv = (const float*)d_in[3];
    const float* Wo = (const float*)d_in[4];
    const int* start_pos = (const int*)d_in[5];
    float* out = (float*)d_out;

    float *qp, *kp, *vp, *cp;
    cudaGetSymbolAddress((void**)&qp, g_q);
    cudaGetSymbolAddress((void**)&kp, g_k);
    cudaGetSymbolAddress((void**)&vp, g_v);
    cudaGetSymbolAddress((void**)&cp, g_ctx);
    __half *xhi, *xlo, *wqhi, *wqlo, *wkhi, *wklo, *wvhi, *wvlo, *wohi, *wolo, *chi, *clo;
    cudaGetSymbolAddress((void**)&xhi, g_xhi);   cudaGetSymbolAddress((void**)&xlo, g_xlo);
    cudaGetSymbolAddress((void**)&wqhi, g_wqhi); cudaGetSymbolAddress((void**)&wqlo, g_wqlo);
    cudaGetSymbolAddress((void**)&wkhi, g_wkhi); cudaGetSymbolAddress((void**)&wklo, g_wklo);
    cudaGetSymbolAddress((void**)&wvhi, g_wvhi); cudaGetSymbolAddress((void**)&wvlo, g_wvlo);
    cudaGetSymbolAddress((void**)&wohi, g_wohi); cudaGetSymbolAddress((void**)&wolo, g_wolo);
    cudaGetSymbolAddress((void**)&chi, g_chi);   cudaGetSymbolAddress((void**)&clo, g_clo);

    cudaFuncSetAttribute(flash_kernel, cudaFuncAttributeMaxDynamicSharedMemorySize,
                         FLASH_SMEM_BYTES);

    rope_table_kernel<<<(SEQ * 32 + 255) / 256, 256>>>(start_pos);

    // fp32 -> fp16 hi/lo splits
    split_kernel<<<(SEQ*DMODEL/4 + 255) / 256, 256>>>(x,  xhi,  xlo,  SEQ*DMODEL/4);
    split_kernel<<<(DMODEL*DMODEL/4 + 255) / 256, 256>>>(Wq, wqhi, wqlo, DMODEL*DMODEL/4);
    split_kernel<<<(KVD*DMODEL/4 + 255) / 256, 256>>>(Wk, wkhi, wklo, KVD*DMODEL/4);
    split_kernel<<<(KVD*DMODEL/4 + 255) / 256, 256>>>(Wv, wvhi, wvlo, KVD*DMODEL/4);
    split_kernel<<<(DMODEL*DMODEL/4 + 255) / 256, 256>>>(Wo, wohi, wolo, DMODEL*DMODEL/4);

    // Q projection
    gemm_hmma<<<dim3(DMODEL/BN, SEQ/BM, 1), 256>>>(
        xhi, xlo, wqhi, wqlo, wqhi, wqlo, qp, qp, SEQ, DMODEL, DMODEL);
    // K and V projections fused via z
    gemm_hmma<<<dim3(KVD/BN, SEQ/BM, 2), 256>>>(
        xhi, xlo, wkhi, wklo, wvhi, wvlo, kp, vp, SEQ, KVD, DMODEL);

    rope_apply_kernel<<<(SEQ * NH  * 32 + 255) / 256, 256>>>(qp, NH);
    rope_apply_kernel<<<(SEQ * NKV * 32 + 255) / 256, 256>>>(kp, NKV);

    flash_kernel<<<dim3(SEQ / 64, NH), 256, FLASH_SMEM_BYTES>>>(qp, kp, vp, cp);

    // O projection
    split_kernel<<<(SEQ*DMODEL/4 + 255) / 256, 256>>>(cp, chi, clo, SEQ*DMODEL/4);
    gemm_hmma<<<dim3(DMODEL/BN, SEQ/BM, 1), 256>>>(
        chi, clo, wohi, wolo, wohi, wolo, out, out, SEQ, DMODEL, DMODEL);
}

// round 4
// speedup vs baseline: 2.5786x; 1.7299x over previous
#include <cuda_runtime.h>
#include <cuda_fp16.h>
#include <math.h>
#include <stdint.h>

#define SEQ    2048
#define DMODEL 2048
#define NH     32
#define NKV    8
#define HD     64
#define KVD    (NKV*HD)   // 512

// -------------------- scratch (no allocs allowed) --------------------
__device__ float g_q[SEQ*DMODEL];
__device__ float g_k[SEQ*KVD];
__device__ float g_v[SEQ*KVD];
__device__ float g_cos[SEQ*(HD/2)];
__device__ float g_sin[SEQ*(HD/2)];

// fp16 split buffers (hi/lo)
__device__ __half g_xhi[SEQ*DMODEL],     g_xlo[SEQ*DMODEL];
__device__ __half g_wqhi[DMODEL*DMODEL], g_wqlo[DMODEL*DMODEL];
__device__ __half g_wkhi[KVD*DMODEL],    g_wklo[KVD*DMODEL];
__device__ __half g_wvhi[KVD*DMODEL],    g_wvlo[KVD*DMODEL];
__device__ __half g_wohi[DMODEL*DMODEL], g_wolo[DMODEL*DMODEL];
__device__ __half g_chi[SEQ*DMODEL],     g_clo[SEQ*DMODEL];
__device__ __half g_qh[SEQ*DMODEL],      g_ql[SEQ*DMODEL];
__device__ __half g_kh[SEQ*KVD],         g_kl[SEQ*KVD];
__device__ __half g_vh[SEQ*KVD],         g_vl[SEQ*KVD];

// ==================== helpers ====================
__device__ __forceinline__ uint32_t smem_u32(const void* p) {
    uint32_t a;
    asm("{ .reg .u64 t; cvta.to.shared.u64 t, %1; cvt.u32.u64 %0, t; }"
        : "=r"(a) : "l"(p));
    return a;
}

#define CP_ASYNC16(dst, src) \
    asm volatile("cp.async.cg.shared.global [%0], [%1], 16;" :: "r"(dst), "l"(src) : "memory")
#define CP_COMMIT() asm volatile("cp.async.commit_group;" ::: "memory")
#define CP_WAIT_1() asm volatile("cp.async.wait_group 1;" ::: "memory")
#define CP_WAIT_0() asm volatile("cp.async.wait_group 0;" ::: "memory")

#define LDSM4(r0, r1, r2, r3, addr) \
    asm volatile("ldmatrix.sync.aligned.m8n8.x4.shared.b16 {%0,%1,%2,%3}, [%4];" \
        : "=r"(r0), "=r"(r1), "=r"(r2), "=r"(r3) : "r"(addr))

#define LDSM4T(r0, r1, r2, r3, addr) \
    asm volatile("ldmatrix.sync.aligned.m8n8.x4.trans.shared.b16 {%0,%1,%2,%3}, [%4];" \
        : "=r"(r0), "=r"(r1), "=r"(r2), "=r"(r3) : "r"(addr))

#define MMA16816(d, a, b0, b1) \
    asm volatile("mma.sync.aligned.m16n8k16.row.col.f32.f16.f16.f32 " \
        "{%0,%1,%2,%3}, {%4,%5,%6,%7}, {%8,%9}, {%0,%1,%2,%3};" \
        : "+f"((d)[0]), "+f"((d)[1]), "+f"((d)[2]), "+f"((d)[3]) \
        : "r"((a)[0]), "r"((a)[1]), "r"((a)[2]), "r"((a)[3]), "r"(b0), "r"(b1))

// ==================== fp32 -> fp16 hi/lo split ====================
__global__ void split_kernel(const float* __restrict__ src,
                             __half* __restrict__ hi,
                             __half* __restrict__ lo, int n4) {
    int i = blockIdx.x * blockDim.x + threadIdx.x;
    if (i >= n4) return;
    float4 x = ((const float4*)src)[i];
    __half h0 = __float2half_rn(x.x), h1 = __float2half_rn(x.y);
    __half h2 = __float2half_rn(x.z), h3 = __float2half_rn(x.w);
    __half2* hp = (__half2*)(hi + i * 4);
    __half2* lp = (__half2*)(lo + i * 4);
    hp[0] = __half2(h0, h1);
    hp[1] = __half2(h2, h3);
    lp[0] = __half2(__float2half_rn(x.x - __half2float(h0)),
                    __float2half_rn(x.y - __half2float(h1)));
    lp[1] = __half2(__float2half_rn(x.z - __half2float(h2)),
                    __float2half_rn(x.w - __half2float(h3)));
}

// ==================== HMMA fp16x3 GEMM (projections) ====================
#define BM 128
#define BN 128
#define BK 32
#define ASTRH 40

__global__ void __launch_bounds__(256) gemm_hmma(
    const __half* __restrict__ Ahi, const __half* __restrict__ Alo,
    const __half* __restrict__ Bhi0, const __half* __restrict__ Blo0,
    const __half* __restrict__ Bhi1, const __half* __restrict__ Blo1,
    float* __restrict__ C0, float* __restrict__ C1,
    int M, int N, int K) {
    __shared__ __half sA[2][BM * ASTRH];
    __shared__ __half sB[2][BN * ASTRH];

    const __half* Bhi = blockIdx.z ? Bhi1 : Bhi0;
    const __half* Blo = blockIdx.z ? Blo1 : Blo0;
    float* C = blockIdx.z ? C1 : C0;

    const int tid = threadIdx.x;
    const int wid = tid >> 5, lane = tid & 31;
    const int wm = (wid & 1) * 64;
    const int wn = (wid >> 1) * 32;
    const int bm = blockIdx.y * BM, bn = blockIdx.x * BN;

    const __half* Asrc[3] = {Ahi, Ahi, Alo};
    const __half* Bsrc[3] = {Bhi, Blo, Bhi};

    const int kiters = K / BK;
    const int NIT = 3 * kiters;

    const int row0 = tid >> 2, part0 = (tid & 3);
    const int row1 = (tid + 256) >> 2, part1 = (tid & 3);

    uint32_t sAu = smem_u32(sA), sBu = smem_u32(sB);
    const uint32_t stageBytes = BM * ASTRH * 2;

    float acc[4][4][4];
#pragma unroll
    for (int a = 0; a < 4; a++)
#pragma unroll
        for (int b = 0; b < 4; b++)
#pragma unroll
            for (int c = 0; c < 4; c++) acc[a][b][c] = 0.f;

#define LOAD_TILES(stage, it) do {                                             \
    int _seg = (it) / kiters; int _k0 = ((it) % kiters) * BK;                  \
    const __half* _A = Asrc[_seg]; const __half* _B = Bsrc[_seg];              \
    uint32_t _sa = sAu + (stage) * stageBytes;                                 \
    uint32_t _sb = sBu + (stage) * stageBytes;                                 \
    CP_ASYNC16(_sa + (row0 * ASTRH + part0 * 8) * 2,                           \
               _A + (size_t)(bm + row0) * K + _k0 + part0 * 8);                \
    CP_ASYNC16(_sa + (row1 * ASTRH + part1 * 8) * 2,                           \
               _A + (size_t)(bm + row1) * K + _k0 + part1 * 8);                \
    CP_ASYNC16(_sb + (row0 * ASTRH + part0 * 8) * 2,                           \
               _B + (size_t)(bn + row0) * K + _k0 + part0 * 8);                \
    CP_ASYNC16(_sb + (row1 * ASTRH + part1 * 8) * 2,                           \
               _B + (size_t)(bn + row1) * K + _k0 + part1 * 8);                \
} while (0)

    LOAD_TILES(0, 0);
    CP_COMMIT();

    for (int it = 0; it < NIT; it++) {
        int stage = it & 1;
        if (it + 1 < NIT) {
            LOAD_TILES(stage ^ 1, it + 1);
            CP_COMMIT();
            CP_WAIT_1();
        } else {
            CP_WAIT_0();
        }
        __syncthreads();

        uint32_t sa = sAu + stage * stageBytes;
        uint32_t sb = sBu + stage * stageBytes;
        int lr = lane & 15, lc = lane >> 4;

#pragma unroll
        for (int k16 = 0; k16 < 2; k16++) {
            uint32_t a[4][4];
#pragma unroll
            for (int mt = 0; mt < 4; mt++) {
                uint32_t addr = sa + ((wm + mt * 16 + lr) * ASTRH
                                      + k16 * 16 + lc * 8) * 2;
                LDSM4(a[mt][0], a[mt][1], a[mt][2], a[mt][3], addr);
            }
            uint32_t b[2][4];
#pragma unroll
            for (int p = 0; p < 2; p++) {
                uint32_t addr = sb + ((wn + p * 16 + lr) * ASTRH
                                      + k16 * 16 + lc * 8) * 2;
                LDSM4(b[p][0], b[p][1], b[p][2], b[p][3], addr);
            }
#pragma unroll
            for (int mt = 0; mt < 4; mt++)
#pragma unroll
                for (int nt = 0; nt < 4; nt++) {
                    int p = nt >> 1, w = nt & 1;
                    MMA16816(acc[mt][nt], a[mt], b[p][w], b[p][w + 2]);
                }
        }
        __syncthreads();
    }

    int er = lane >> 2, ec = (lane & 3) * 2;
#pragma unroll
    for (int mt = 0; mt < 4; mt++) {
#pragma unroll
        for (int nt = 0; nt < 4; nt++) {
            int r = bm + wm + mt * 16 + er;
            int c = bn + wn + nt * 8 + ec;
            *(float2*)&C[(size_t)r * N + c]       = make_float2(acc[mt][nt][0], acc[mt][nt][1]);
            *(float2*)&C[(size_t)(r + 8) * N + c] = make_float2(acc[mt][nt][2], acc[mt][nt][3]);
        }
    }
}

// -------------------- RoPE --------------------
__global__ void rope_table_kernel(const int* __restrict__ start_pos) {
    int idx = blockIdx.x * blockDim.x + threadIdx.x;
    if (idx >= SEQ * 32) return;
    int t = idx >> 5, j = idx & 31;
    const double PI = 3.14159265358979323846;
    double e = (double)(2 * j) / 64.0;
    double invf = pow(500000.0, -e);
    double wavelen = 2.0 * PI / invf;
    double inv;
    if (wavelen > 8192.0) {
        inv = invf / 32.0;
    } else if (wavelen < 2048.0) {
        inv = invf;
    } else {
        double smooth = (8192.0 / wavelen - 1.0) / 3.0;
        inv = (1.0 - smooth) * (invf / 32.0) + smooth * invf;
    }
    float angle = (float)(start_pos[0] + t) * (float)inv;
    g_cos[idx] = (float)cos((double)angle);
    g_sin[idx] = (float)sin((double)angle);
}

__global__ void rope_apply_kernel(float* __restrict__ buf, int n_heads) {
    int idx = blockIdx.x * blockDim.x + threadIdx.x;
    int total = SEQ * n_heads * 32;
    if (idx >= total) return;
    int j = idx & 31;
    int h = (idx >> 5) % n_heads;
    int t = idx / (32 * n_heads);
    float c = g_cos[t * 32 + j];
    float s = g_sin[t * 32 + j];
    float* p = buf + (size_t)t * n_heads * 64 + h * 64 + j;
    float x1 = p[0], x2 = p[32];
    p[0]  = x1 * c - x2 * s;
    p[32] = x2 * c + x1 * s;
}

// ==================== HMMA flash attention ====================
// 64x64 tiles, 4 warps (16 rows each), fp16 hi/lo 3-term for S and PV.
#define FATR 72                      // padded halves per row (144B)
#define FTILE (64 * FATR * 2)        // tile bytes = 9216
#define FLASH_SMEM (FTILE * 10)      // Qh,Ql + 2 stages x (Kh,Kl,Vh,Vl)

__global__ void __launch_bounds__(128) flash_hmma(
    const __half* __restrict__ qhi, const __half* __restrict__ qlo,
    const __half* __restrict__ khi, const __half* __restrict__ klo,
    const __half* __restrict__ vhi, const __half* __restrict__ vlo,
    __half* __restrict__ chi, __half* __restrict__ clo) {
    extern __shared__ __half fsm[];
    const int h  = blockIdx.x;
    const int qb = gridDim.y - 1 - blockIdx.y;   // big tiles first
    const int g  = h >> 2;
    const int tid = threadIdx.x;
    const int wid = tid >> 5, lane = tid & 31;
    const int wm = wid * 16;
    const int er = lane >> 2, ec = (lane & 3) * 2;
    const int lr = lane & 15, lc = lane >> 4;

    uint32_t sb = smem_u32(fsm);
    uint32_t sQh = sb, sQl = sb + FTILE;

    // Q tiles (hi, lo)
#pragma unroll
    for (int l = 0; l < 4; l++) {
        int c = tid + l * 128;
        int row = c >> 3, cc = c & 7;
        size_t off = (size_t)(qb * 64 + row) * DMODEL + h * 64 + cc * 8;
        CP_ASYNC16(sQh + row * FATR * 2 + cc * 16, qhi + off);
        CP_ASYNC16(sQl + row * FATR * 2 + cc * 16, qlo + off);
    }
    // KV stage loader
#define KV_LOAD(kb_, st_) do {                                                  \
    uint32_t base = sb + 2 * FTILE + (st_) * 4 * FTILE;                         \
    _Pragma("unroll")                                                           \
    for (int l = 0; l < 4; l++) {                                               \
        int c = tid + l * 128;                                                  \
        int row = c >> 3, cc = c & 7;                                           \
        size_t off = (size_t)((kb_) * 64 + row) * KVD + g * 64 + cc * 8;        \
        uint32_t d = row * FATR * 2 + cc * 16;                                  \
        CP_ASYNC16(base + 0 * FTILE + d, khi + off);                            \
        CP_ASYNC16(base + 1 * FTILE + d, klo + off);                            \
        CP_ASYNC16(base + 2 * FTILE + d, vhi + off);                            \
        CP_ASYNC16(base + 3 * FTILE + d, vlo + off);                            \
    }                                                                           \
} while (0)

    KV_LOAD(0, 0);
    CP_COMMIT();

    uint32_t aQh[4][4], aQl[4][4];
    float oacc[8][4];
    float mi0 = -INFINITY, mi1 = -INFINITY, li0 = 0.f, li1 = 0.f;
#pragma unroll
    for (int nt = 0; nt < 8; nt++)
#pragma unroll
        for (int j = 0; j < 4; j++) oacc[nt][j] = 0.f;

    for (int kb = 0; kb <= qb; kb++) {
        int stage = kb & 1;
        if (kb < qb) { KV_LOAD(kb + 1, stage ^ 1); CP_COMMIT(); CP_WAIT_1(); }
        else         { CP_WAIT_0(); }
        __syncthreads();

        if (kb == 0) {  // hoist Q fragments once smem is ready
#pragma unroll
            for (int k16 = 0; k16 < 4; k16++) {
                uint32_t ah = sQh + ((wm + lr) * FATR + k16 * 16 + lc * 8) * 2;
                LDSM4(aQh[k16][0], aQh[k16][1], aQh[k16][2], aQh[k16][3], ah);
                uint32_t al = sQl + ((wm + lr) * FATR + k16 * 16 + lc * 8) * 2;
                LDSM4(aQl[k16][0], aQl[k16][1], aQl[k16][2], aQl[k16][3], al);
            }
        }

        uint32_t base = sb + 2 * FTILE + stage * 4 * FTILE;
        uint32_t sKh = base, sKl = base + FTILE;
        uint32_t sVh = base + 2 * FTILE, sVl = base + 3 * FTILE;

        // ---- S = Q K^T (3-term) ----
        float sacc[8][4];
#pragma unroll
        for (int nt = 0; nt < 8; nt++)
#pragma unroll
            for (int j = 0; j < 4; j++) sacc[nt][j] = 0.f;

#pragma unroll
        for (int k16 = 0; k16 < 4; k16++) {
            uint32_t bh[4][4], bl[4][4];
#pragma unroll
            for (int p = 0; p < 4; p++) {
                uint32_t adr = sKh + ((p * 16 + lr) * FATR + k16 * 16 + lc * 8) * 2;
                LDSM4(bh[p][0], bh[p][1], bh[p][2], bh[p][3], adr);
                adr = sKl + ((p * 16 + lr) * FATR + k16 * 16 + lc * 8) * 2;
                LDSM4(bl[p][0], bl[p][1], bl[p][2], bl[p][3], adr);
            }
#pragma unroll
            for (int nt = 0; nt < 8; nt++) {
                int p = nt >> 1, w = nt & 1;
                MMA16816(sacc[nt], aQh[k16], bh[p][w], bh[p][w + 2]);
                MMA16816(sacc[nt], aQh[k16], bl[p][w], bl[p][w + 2]);
                MMA16816(sacc[nt], aQl[k16], bh[p][w], bh[p][w + 2]);
            }
        }

        // ---- mask + scale ----
        if (kb == qb) {
#pragma unroll
            for (int nt = 0; nt < 8; nt++) {
                int c0 = nt * 8 + ec;
                sacc[nt][0] = (c0     <= wm + er)     ? sacc[nt][0] * 0.125f : -INFINITY;
                sacc[nt][1] = (c0 + 1 <= wm + er)     ? sacc[nt][1] * 0.125f : -INFINITY;
                sacc[nt][2] = (c0     <= wm + er + 8) ? sacc[nt][2] * 0.125f : -INFINITY;
                sacc[nt][3] = (c0 + 1 <= wm + er + 8) ? sacc[nt][3] * 0.125f : -INFINITY;
            }
        } else {
#pragma unroll
            for (int nt = 0; nt < 8; nt++)
#pragma unroll
                for (int j = 0; j < 4; j++) sacc[nt][j] *= 0.125f;
        }

        // ---- online softmax (rows er, er+8) ----
        float mx0 = -INFINITY, mx1 = -INFINITY;
#pragma unroll
        for (int nt = 0; nt < 8; nt++) {
            mx0 = fmaxf(mx0, fmaxf(sacc[nt][0], sacc[nt][1]));
            mx1 = fmaxf(mx1, fmaxf(sacc[nt][2], sacc[nt][3]));
        }
#pragma unroll
        for (int off = 1; off < 4; off <<= 1) {
            mx0 = fmaxf(mx0, __shfl_xor_sync(0xffffffffu, mx0, off));
            mx1 = fmaxf(mx1, __shfl_xor_sync(0xffffffffu, mx1, off));
        }
        float mn0 = fmaxf(mi0, mx0), mn1 = fmaxf(mi1, mx1);
        float sum0 = 0.f, sum1 = 0.f;
#pragma unroll
        for (int nt = 0; nt < 8; nt++) {
            sacc[nt][0] = __expf(sacc[nt][0] - mn0);
            sacc[nt][1] = __expf(sacc[nt][1] - mn0);
            sacc[nt][2] = __expf(sacc[nt][2] - mn1);
            sacc[nt][3] = __expf(sacc[nt][3] - mn1);
            sum0 += sacc[nt][0] + sacc[nt][1];
            sum1 += sacc[nt][2] + sacc[nt][3];
        }
#pragma unroll
        for (int off = 1; off < 4; off <<= 1) {
            sum0 += __shfl_xor_sync(0xffffffffu, sum0, off);
            sum1 += __shfl_xor_sync(0xffffffffu, sum1, off);
        }
        float sc0 = __expf(mi0 - mn0), sc1 = __expf(mi1 - mn1);
        li0 = li0 * sc0 + sum0; li1 = li1 * sc1 + sum1;
        mi0 = mn0; mi1 = mn1;
#pragma unroll
        for (int nt = 0; nt < 8; nt++) {
            oacc[nt][0] *= sc0; oacc[nt][1] *= sc0;
            oacc[nt][2] *= sc1; oacc[nt][3] *= sc1;
        }

        // ---- O += P V (3-term), P fragments built from sacc in-register ----
#pragma unroll
        for (int k16 = 0; k16 < 4; k16++) {
            uint32_t ph[4], pl[4];
#pragma unroll
            for (int half16 = 0; half16 < 2; half16++) {
                int st = 2 * k16 + half16;
                __half2 h01 = __floats2half2_rn(sacc[st][0], sacc[st][1]);
                float2 f01 = __half22float2(h01);
                __half2 l01 = __floats2half2_rn(sacc[st][0] - f01.x, sacc[st][1] - f01.y);
                __half2 h23 = __floats2half2_rn(sacc[st][2], sacc[st][3]);
                float2 f23 = __half22float2(h23);
                __half2 l23 = __floats2half2_rn(sacc[st][2] - f23.x, sacc[st][3] - f23.y);
                ph[half16 * 2]     = *(uint32_t*)&h01;
                ph[half16 * 2 + 1] = *(uint32_t*)&h23;
                pl[half16 * 2]     = *(uint32_t*)&l01;
                pl[half16 * 2 + 1] = *(uint32_t*)&l23;
            }
            uint32_t bvh[4][4], bvl[4][4];
#pragma unroll
            for (int p = 0; p < 4; p++) {
                uint32_t adr = sVh + ((k16 * 16 + lr) * FATR + p * 16 + lc * 8) * 2;
                LDSM4T(bvh[p][0], bvh[p][1], bvh[p][2], bvh[p][3], adr);
                adr = sVl + ((k16 * 16 + lr) * FATR + p * 16 + lc * 8) * 2;
                LDSM4T(bvl[p][0], bvl[p][1], bvl[p][2], bvl[p][3], adr);
            }
#pragma unroll
            for (int nt = 0; nt < 8; nt++) {
                int p = nt >> 1, w = (nt & 1) * 2;
                MMA16816(oacc[nt], ph, bvh[p][w], bvh[p][w + 1]);
                MMA16816(oacc[nt], ph, bvl[p][w], bvl[p][w + 1]);
                MMA16816(oacc[nt], pl, bvh[p][w], bvh[p][w + 1]);
            }
        }
        __syncthreads();   // finish reading this stage before it is refilled
    }

    // ---- epilogue: normalize, hi/lo split, store ----
    float inv0 = 1.0f / li0, inv1 = 1.0f / li1;
    int r0g = qb * 64 + wm + er, r1g = r0g + 8;
#pragma unroll
    for (int nt = 0; nt < 8; nt++) {
        int c = h * 64 + nt * 8 + ec;
        float v0 = oacc[nt][0] * inv0, v1 = oacc[nt][1] * inv0;
        float v2 = oacc[nt][2] * inv1, v3 = oacc[nt][3] * inv1;
        __half2 h0 = __floats2half2_rn(v0, v1);
        float2 f0 = __half22float2(h0);
        __half2 l0 = __floats2half2_rn(v0 - f0.x, v1 - f0.y);
        __half2 h1 = __floats2half2_rn(v2, v3);
        float2 f1 = __half22float2(h1);
        __half2 l1 = __floats2half2_rn(v2 - f1.x, v3 - f1.y);
        *(__half2*)&chi[(size_t)r0g * DMODEL + c] = h0;
        *(__half2*)&clo[(size_t)r0g * DMODEL + c] = l0;
        *(__half2*)&chi[(size_t)r1g * DMODEL + c] = h1;
        *(__half2*)&clo[(size_t)r1g * DMODEL + c] = l1;
    }
}

// -------------------- launch --------------------
extern "C" void kernel_launch(void* const* d_in, const int* in_sizes, int n_in,
                              void* d_out, int out_size) {
    const float* x  = (const float*)d_in[0];
    const float* Wq = (const float*)d_in[1];
    const float* Wk = (const float*)d_in[2];
    const float* Wv = (const float*)d_in[3];
    const float* Wo = (const float*)d_in[4];
    const int* start_pos = (const int*)d_in[5];
    float* out = (float*)d_out;

    float *qp, *kp, *vp;
    cudaGetSymbolAddress((void**)&qp, g_q);
    cudaGetSymbolAddress((void**)&kp, g_k);
    cudaGetSymbolAddress((void**)&vp, g_v);
    __half *xhi, *xlo, *wqhi, *wqlo, *wkhi, *wklo, *wvhi, *wvlo, *wohi, *wolo;
    __half *chi, *clo, *qh, *ql, *kh, *kl, *vh, *vl;
    cudaGetSymbolAddress((void**)&xhi, g_xhi);   cudaGetSymbolAddress((void**)&xlo, g_xlo);
    cudaGetSymbolAddress((void**)&wqhi, g_wqhi); cudaGetSymbolAddress((void**)&wqlo, g_wqlo);
    cudaGetSymbolAddress((void**)&wkhi, g_wkhi); cudaGetSymbolAddress((void**)&wklo, g_wklo);
    cudaGetSymbolAddress((void**)&wvhi, g_wvhi); cudaGetSymbolAddress((void**)&wvlo, g_wvlo);
    cudaGetSymbolAddress((void**)&wohi, g_wohi); cudaGetSymbolAddress((void**)&wolo, g_wolo);
    cudaGetSymbolAddress((void**)&chi, g_chi);   cudaGetSymbolAddress((void**)&clo, g_clo);
    cudaGetSymbolAddress((void**)&qh, g_qh);     cudaGetSymbolAddress((void**)&ql, g_ql);
    cudaGetSymbolAddress((void**)&kh, g_kh);     cudaGetSymbolAddress((void**)&kl, g_kl);
    cudaGetSymbolAddress((void**)&vh, g_vh);     cudaGetSymbolAddress((void**)&vl, g_vl);

    cudaFuncSetAttribute(flash_hmma, cudaFuncAttributeMaxDynamicSharedMemorySize,
                         FLASH_SMEM);

    rope_table_kernel<<<(SEQ * 32 + 255) / 256, 256>>>(start_pos);

    // fp32 -> fp16 hi/lo splits of inputs/weights
    split_kernel<<<(SEQ*DMODEL/4 + 255) / 256, 256>>>(x,  xhi,  xlo,  SEQ*DMODEL/4);
    split_kernel<<<(DMODEL*DMODEL/4 + 255) / 256, 256>>>(Wq, wqhi, wqlo, DMODEL*DMODEL/4);
    split_kernel<<<(KVD*DMODEL/4 + 255) / 256, 256>>>(Wk, wkhi, wklo, KVD*DMODEL/4);
    split_kernel<<<(KVD*DMODEL/4 + 255) / 256, 256>>>(Wv, wvhi, wvlo, KVD*DMODEL/4);
    split_kernel<<<(DMODEL*DMODEL/4 + 255) / 256, 256>>>(Wo, wohi, wolo, DMODEL*DMODEL/4);

    // projections
    gemm_hmma<<<dim3(DMODEL/BN, SEQ/BM, 1), 256>>>(
        xhi, xlo, wqhi, wqlo, wqhi, wqlo, qp, qp, SEQ, DMODEL, DMODEL);
    gemm_hmma<<<dim3(KVD/BN, SEQ/BM, 2), 256>>>(
        xhi, xlo, wkhi, wklo, wvhi, wvlo, kp, vp, SEQ, KVD, DMODEL);

    // RoPE on fp32 q/k
    rope_apply_kernel<<<(SEQ * NH  * 32 + 255) / 256, 256>>>(qp, NH);
    rope_apply_kernel<<<(SEQ * NKV * 32 + 255) / 256, 256>>>(kp, NKV);

    // split q/k/v to fp16 hi/lo for flash
    split_kernel<<<(SEQ*DMODEL/4 + 255) / 256, 256>>>(qp, qh, ql, SEQ*DMODEL/4);
    split_kernel<<<(SEQ*KVD/4 + 255) / 256, 256>>>(kp, kh, kl, SEQ*KVD/4);
    split_kernel<<<(SEQ*KVD/4 + 255) / 256, 256>>>(vp, vh, vl, SEQ*KVD/4);

    // flash attention -> ctx hi/lo directly
    flash_hmma<<<dim3(NH, SEQ / 64), 128, FLASH_SMEM>>>(qh, ql, kh, kl, vh, vl, chi, clo);

    // O projection
    gemm_hmma<<<dim3(DMODEL/BN, SEQ/BM, 1), 256>>>(
        chi, clo, wohi, wolo, wohi, wolo, out, out, SEQ, DMODEL, DMODEL);
}

// round 5
// speedup vs baseline: 3.0662x; 1.1891x over previous
#include <cuda_runtime.h>
#include <cuda_fp16.h>
#include <math.h>
#include <stdint.h>

#define SEQ    2048
#define DMODEL 2048
#define NH     32
#define NKV    8
#define HD     64
#define KVD    (NKV*HD)   // 512

// -------------------- scratch (no allocs allowed) --------------------
__device__ float g_q[SEQ*DMODEL];
__device__ float g_k[SEQ*KVD];
__device__ float g_v[SEQ*KVD];
__device__ float g_cos[SEQ*(HD/2)];
__device__ float g_sin[SEQ*(HD/2)];

// fp16 split buffers (hi/lo)
__device__ __half g_xhi[SEQ*DMODEL],     g_xlo[SEQ*DMODEL];
__device__ __half g_wqhi[DMODEL*DMODEL], g_wqlo[DMODEL*DMODEL];
__device__ __half g_wkhi[KVD*DMODEL],    g_wklo[KVD*DMODEL];
__device__ __half g_wvhi[KVD*DMODEL],    g_wvlo[KVD*DMODEL];
__device__ __half g_wohi[DMODEL*DMODEL], g_wolo[DMODEL*DMODEL];
__device__ __half g_chi[SEQ*DMODEL],     g_clo[SEQ*DMODEL];
__device__ __half g_qh[SEQ*DMODEL],      g_ql[SEQ*DMODEL];
__device__ __half g_kh[SEQ*KVD],         g_kl[SEQ*KVD];
__device__ __half g_vh[SEQ*KVD],         g_vl[SEQ*KVD];

// ==================== helpers ====================
__device__ __forceinline__ uint32_t smem_u32(const void* p) {
    uint32_t a;
    asm("{ .reg .u64 t; cvta.to.shared.u64 t, %1; cvt.u32.u64 %0, t; }"
        : "=r"(a) : "l"(p));
    return a;
}

#define CP_ASYNC16(dst, src) \
    asm volatile("cp.async.cg.shared.global [%0], [%1], 16;" :: "r"(dst), "l"(src) : "memory")
#define CP_COMMIT() asm volatile("cp.async.commit_group;" ::: "memory")
#define CP_WAIT_1() asm volatile("cp.async.wait_group 1;" ::: "memory")
#define CP_WAIT_0() asm volatile("cp.async.wait_group 0;" ::: "memory")

#define LDSM4(r0, r1, r2, r3, addr) \
    asm volatile("ldmatrix.sync.aligned.m8n8.x4.shared.b16 {%0,%1,%2,%3}, [%4];" \
        : "=r"(r0), "=r"(r1), "=r"(r2), "=r"(r3) : "r"(addr))

#define LDSM4T(r0, r1, r2, r3, addr) \
    asm volatile("ldmatrix.sync.aligned.m8n8.x4.trans.shared.b16 {%0,%1,%2,%3}, [%4];" \
        : "=r"(r0), "=r"(r1), "=r"(r2), "=r"(r3) : "r"(addr))

#define MMA16816(d, a, b0, b1) \
    asm volatile("mma.sync.aligned.m16n8k16.row.col.f32.f16.f16.f32 " \
        "{%0,%1,%2,%3}, {%4,%5,%6,%7}, {%8,%9}, {%0,%1,%2,%3};" \
        : "+f"((d)[0]), "+f"((d)[1]), "+f"((d)[2]), "+f"((d)[3]) \
        : "r"((a)[0]), "r"((a)[1]), "r"((a)[2]), "r"((a)[3]), "r"(b0), "r"(b1))

// ==================== fp32 -> fp16 hi/lo split ====================
__device__ __forceinline__ void split4(const float* __restrict__ src,
                                       __half* __restrict__ hi,
                                       __half* __restrict__ lo, int i) {
    float4 x = ((const float4*)src)[i];
    __half h0 = __float2half_rn(x.x), h1 = __float2half_rn(x.y);
    __half h2 = __float2half_rn(x.z), h3 = __float2half_rn(x.w);
    __half2* hp = (__half2*)(hi + i * 4);
    __half2* lp = (__half2*)(lo + i * 4);
    hp[0] = __half2(h0, h1);
    hp[1] = __half2(h2, h3);
    lp[0] = __half2(__float2half_rn(x.x - __half2float(h0)),
                    __float2half_rn(x.y - __half2float(h1)));
    lp[1] = __half2(__float2half_rn(x.z - __half2float(h2)),
                    __float2half_rn(x.w - __half2float(h3)));
}

__global__ void split_kernel(const float* __restrict__ src,
                             __half* __restrict__ hi,
                             __half* __restrict__ lo, int n4) {
    int i = blockIdx.x * blockDim.x + threadIdx.x;
    if (i < n4) split4(src, hi, lo, i);
}

// all 4 weight splits in one launch
#define WQ4 (DMODEL*DMODEL/4)   // 1048576
#define WK4 (KVD*DMODEL/4)      // 262144
__global__ void split_w_kernel(const float* __restrict__ Wq, const float* __restrict__ Wk,
                               const float* __restrict__ Wv, const float* __restrict__ Wo,
                               __half* __restrict__ qh, __half* __restrict__ ql,
                               __half* __restrict__ kh, __half* __restrict__ kl,
                               __half* __restrict__ vh, __half* __restrict__ vl,
                               __half* __restrict__ oh, __half* __restrict__ ol) {
    int i = blockIdx.x * blockDim.x + threadIdx.x;
    if (i < WQ4)                      split4(Wq, qh, ql, i);
    else if (i < WQ4 + WK4)           split4(Wk, kh, kl, i - WQ4);
    else if (i < WQ4 + 2*WK4)         split4(Wv, vh, vl, i - WQ4 - WK4);
    else if (i < 2*WQ4 + 2*WK4)       split4(Wo, oh, ol, i - WQ4 - 2*WK4);
}

// ==================== HMMA fp16x3 GEMM (projections) ====================
// Shared-tile version: per K-chunk load Ahi/Alo/Bhi/Blo once, run 3 terms.
#define BK 32
#define ASTRH 40
#define TILEB (128 * ASTRH * 2)     // 10240 bytes
#define GSMEM (TILEB * 8)           // 2 stages x 4 tiles = 81920

__global__ void __launch_bounds__(256, 2) gemm3(
    const __half* __restrict__ Ahi, const __half* __restrict__ Alo,
    const __half* __restrict__ B0h, const __half* __restrict__ B0l,
    float* __restrict__ C0, int N0, int nx0,
    const __half* __restrict__ B1h, const __half* __restrict__ B1l,
    float* __restrict__ C1, int N1, int nx1,
    const __half* __restrict__ B2h, const __half* __restrict__ B2l,
    float* __restrict__ C2, int N2,
    int K) {
    extern __shared__ __half gsm[];
    const int bx = blockIdx.x;
    const __half *Bh, *Bl; float* C; int Nc, bnl;
    if (bx < nx0)            { Bh = B0h; Bl = B0l; C = C0; Nc = N0; bnl = bx * 128; }
    else if (bx < nx0 + nx1) { Bh = B1h; Bl = B1l; C = C1; Nc = N1; bnl = (bx - nx0) * 128; }
    else                     { Bh = B2h; Bl = B2l; C = C2; Nc = N2; bnl = (bx - nx0 - nx1) * 128; }

    const int tid = threadIdx.x;
    const int wid = tid >> 5, lane = tid & 31;
    const int wm = (wid & 1) * 64;
    const int wn = (wid >> 1) * 32;
    const int bm = blockIdx.y * 128;
    const int lr = lane & 15, lc = lane >> 4;

    uint32_t sbu = smem_u32(gsm);
    const int r0_ = tid >> 2, r1_ = r0_ + 64;
    const int pp = (tid & 3) * 8;

    float acc[4][4][4];
#pragma unroll
    for (int a = 0; a < 4; a++)
#pragma unroll
        for (int b = 0; b < 4; b++)
#pragma unroll
            for (int c = 0; c < 4; c++) acc[a][b][c] = 0.f;

#define LOADCHUNK(st, k0) do {                                                  \
    uint32_t _b = sbu + (st) * (4 * TILEB);                                     \
    CP_ASYNC16(_b + (r0_ * ASTRH + pp) * 2,                                     \
               Ahi + (size_t)(bm + r0_) * K + (k0) + pp);                       \
    CP_ASYNC16(_b + (r1_ * ASTRH + pp) * 2,                                     \
               Ahi + (size_t)(bm + r1_) * K + (k0) + pp);                       \
    CP_ASYNC16(_b + TILEB + (r0_ * ASTRH + pp) * 2,                             \
               Alo + (size_t)(bm + r0_) * K + (k0) + pp);                       \
    CP_ASYNC16(_b + TILEB + (r1_ * ASTRH + pp) * 2,                             \
               Alo + (size_t)(bm + r1_) * K + (k0) + pp);                       \
    CP_ASYNC16(_b + 2 * TILEB + (r0_ * ASTRH + pp) * 2,                         \
               Bh + (size_t)(bnl + r0_) * K + (k0) + pp);                       \
    CP_ASYNC16(_b + 2 * TILEB + (r1_ * ASTRH + pp) * 2,                         \
               Bh + (size_t)(bnl + r1_) * K + (k0) + pp);                       \
    CP_ASYNC16(_b + 3 * TILEB + (r0_ * ASTRH + pp) * 2,                         \
               Bl + (size_t)(bnl + r0_) * K + (k0) + pp);                       \
    CP_ASYNC16(_b + 3 * TILEB + (r1_ * ASTRH + pp) * 2,                         \
               Bl + (size_t)(bnl + r1_) * K + (k0) + pp);                       \
} while (0)

    const int kiters = K / BK;
    LOADCHUNK(0, 0);
    CP_COMMIT();

    for (int i = 0; i < kiters; i++) {
        int s = i & 1;
        if (i + 1 < kiters) {
            LOADCHUNK(s ^ 1, (i + 1) * BK);
            CP_COMMIT();
            CP_WAIT_1();
        } else {
            CP_WAIT_0();
        }
        __syncthreads();

        uint32_t base = sbu + s * (4 * TILEB);
#pragma unroll
        for (int k16 = 0; k16 < 2; k16++) {
            int koff = k16 * 16 + lc * 8;
            uint32_t aH[4][4], aL[4][4], bH[2][4], bL[2][4];
#pragma unroll
            for (int mt = 0; mt < 4; mt++) {
                uint32_t adr = base + ((wm + mt * 16 + lr) * ASTRH + koff) * 2;
                LDSM4(aH[mt][0], aH[mt][1], aH[mt][2], aH[mt][3], adr);
            }
#pragma unroll
            for (int p = 0; p < 2; p++) {
                uint32_t adr = base + 2 * TILEB + ((wn + p * 16 + lr) * ASTRH + koff) * 2;
                LDSM4(bH[p][0], bH[p][1], bH[p][2], bH[p][3], adr);
            }
#pragma unroll
            for (int mt = 0; mt < 4; mt++)
#pragma unroll
                for (int nt = 0; nt < 4; nt++) {
                    int p = nt >> 1, w = nt & 1;
                    MMA16816(acc[mt][nt], aH[mt], bH[p][w], bH[p][w + 2]);
                }
#pragma unroll
            for (int p = 0; p < 2; p++) {
                uint32_t adr = base + 3 * TILEB + ((wn + p * 16 + lr) * ASTRH + koff) * 2;
                LDSM4(bL[p][0], bL[p][1], bL[p][2], bL[p][3], adr);
            }
#pragma unroll
            for (int mt = 0; mt < 4; mt++)
#pragma unroll
                for (int nt = 0; nt < 4; nt++) {
                    int p = nt >> 1, w = nt & 1;
                    MMA16816(acc[mt][nt], aH[mt], bL[p][w], bL[p][w + 2]);
                }
#pragma unroll
            for (int mt = 0; mt < 4; mt++) {
                uint32_t adr = base + TILEB + ((wm + mt * 16 + lr) * ASTRH + koff) * 2;
                LDSM4(aL[mt][0], aL[mt][1], aL[mt][2], aL[mt][3], adr);
            }
#pragma unroll
            for (int mt = 0; mt < 4; mt++)
#pragma unroll
                for (int nt = 0; nt < 4; nt++) {
                    int p = nt >> 1, w = nt & 1;
                    MMA16816(acc[mt][nt], aL[mt], bH[p][w], bH[p][w + 2]);
                }
        }
        __syncthreads();
    }

    int er = lane >> 2, ec = (lane & 3) * 2;
#pragma unroll
    for (int mt = 0; mt < 4; mt++) {
#pragma unroll
        for (int nt = 0; nt < 4; nt++) {
            int r = bm + wm + mt * 16 + er;
            int c = bnl + wn + nt * 8 + ec;
            *(float2*)&C[(size_t)r * Nc + c]       = make_float2(acc[mt][nt][0], acc[mt][nt][1]);
            *(float2*)&C[(size_t)(r + 8) * Nc + c] = make_float2(acc[mt][nt][2], acc[mt][nt][3]);
        }
    }
}

// -------------------- RoPE --------------------
__global__ void rope_table_kernel(const int* __restrict__ start_pos) {
    int idx = blockIdx.x * blockDim.x + threadIdx.x;
    if (idx >= SEQ * 32) return;
    int t = idx >> 5, j = idx & 31;
    const double PI = 3.14159265358979323846;
    double e = (double)(2 * j) / 64.0;
    double invf = pow(500000.0, -e);
    double wavelen = 2.0 * PI / invf;
    double inv;
    if (wavelen > 8192.0) {
        inv = invf / 32.0;
    } else if (wavelen < 2048.0) {
        inv = invf;
    } else {
        double smooth = (8192.0 / wavelen - 1.0) / 3.0;
        inv = (1.0 - smooth) * (invf / 32.0) + smooth * invf;
    }
    float angle = (float)(start_pos[0] + t) * (float)inv;
    g_cos[idx] = (float)cos((double)angle);
    g_sin[idx] = (float)sin((double)angle);
}

// fused RoPE + fp16 hi/lo split
__global__ void rope_split_kernel(const float* __restrict__ buf,
                                  __half* __restrict__ hi,
                                  __half* __restrict__ lo, int n_heads) {
    int idx = blockIdx.x * blockDim.x + threadIdx.x;
    int total = SEQ * n_heads * 32;
    if (idx >= total) return;
    int j = idx & 31;
    int h = (idx >> 5) % n_heads;
    int t = idx / (32 * n_heads);
    float c = g_cos[t * 32 + j];
    float s = g_sin[t * 32 + j];
    size_t off = (size_t)t * n_heads * 64 + h * 64 + j;
    const float* p = buf + off;
    float x1 = p[0], x2 = p[32];
    float y1 = x1 * c - x2 * s;
    float y2 = x2 * c + x1 * s;
    __half h1 = __float2half_rn(y1), h2 = __float2half_rn(y2);
    hi[off]      = h1;
    hi[off + 32] = h2;
    lo[off]      = __float2half_rn(y1 - __half2float(h1));
    lo[off + 32] = __float2half_rn(y2 - __half2float(h2));
}

// ==================== HMMA flash attention ====================
#define FATR 72
#define FTILE (64 * FATR * 2)
#define FLASH_SMEM (FTILE * 10)

__global__ void __launch_bounds__(128) flash_hmma(
    const __half* __restrict__ qhi, const __half* __restrict__ qlo,
    const __half* __restrict__ khi, const __half* __restrict__ klo,
    const __half* __restrict__ vhi, const __half* __restrict__ vlo,
    __half* __restrict__ chi, __half* __restrict__ clo) {
    extern __shared__ __half fsm[];
    const int h  = blockIdx.x;
    const int qb = gridDim.y - 1 - blockIdx.y;
    const int g  = h >> 2;
    const int tid = threadIdx.x;
    const int wid = tid >> 5, lane = tid & 31;
    const int wm = wid * 16;
    const int er = lane >> 2, ec = (lane & 3) * 2;
    const int lr = lane & 15, lc = lane >> 4;

    uint32_t sb = smem_u32(fsm);
    uint32_t sQh = sb, sQl = sb + FTILE;

#pragma unroll
    for (int l = 0; l < 4; l++) {
        int c = tid + l * 128;
        int row = c >> 3, cc = c & 7;
        size_t off = (size_t)(qb * 64 + row) * DMODEL + h * 64 + cc * 8;
        CP_ASYNC16(sQh + row * FATR * 2 + cc * 16, qhi + off);
        CP_ASYNC16(sQl + row * FATR * 2 + cc * 16, qlo + off);
    }
#define KV_LOAD(kb_, st_) do {                                                  \
    uint32_t base = sb + 2 * FTILE + (st_) * 4 * FTILE;                         \
    _Pragma("unroll")                                                           \
    for (int l = 0; l < 4; l++) {                                               \
        int c = tid + l * 128;                                                  \
        int row = c >> 3, cc = c & 7;                                           \
        size_t off = (size_t)((kb_) * 64 + row) * KVD + g * 64 + cc * 8;        \
        uint32_t d = row * FATR * 2 + cc * 16;                                  \
        CP_ASYNC16(base + 0 * FTILE + d, khi + off);                            \
        CP_ASYNC16(base + 1 * FTILE + d, klo + off);                            \
        CP_ASYNC16(base + 2 * FTILE + d, vhi + off);                            \
        CP_ASYNC16(base + 3 * FTILE + d, vlo + off);                            \
    }                                                                           \
} while (0)

    KV_LOAD(0, 0);
    CP_COMMIT();

    uint32_t aQh[4][4], aQl[4][4];
    float oacc[8][4];
    float mi0 = -INFINITY, mi1 = -INFINITY, li0 = 0.f, li1 = 0.f;
#pragma unroll
    for (int nt = 0; nt < 8; nt++)
#pragma unroll
        for (int j = 0; j < 4; j++) oacc[nt][j] = 0.f;

    for (int kb = 0; kb <= qb; kb++) {
        int stage = kb & 1;
        if (kb < qb) { KV_LOAD(kb + 1, stage ^ 1); CP_COMMIT(); CP_WAIT_1(); }
        else         { CP_WAIT_0(); }
        __syncthreads();

        if (kb == 0) {
#pragma unroll
            for (int k16 = 0; k16 < 4; k16++) {
                uint32_t ah = sQh + ((wm + lr) * FATR + k16 * 16 + lc * 8) * 2;
                LDSM4(aQh[k16][0], aQh[k16][1], aQh[k16][2], aQh[k16][3], ah);
                uint32_t al = sQl + ((wm + lr) * FATR + k16 * 16 + lc * 8) * 2;
                LDSM4(aQl[k16][0], aQl[k16][1], aQl[k16][2], aQl[k16][3], al);
            }
        }

        uint32_t base = sb + 2 * FTILE + stage * 4 * FTILE;
        uint32_t sKh = base, sKl = base + FTILE;
        uint32_t sVh = base + 2 * FTILE, sVl = base + 3 * FTILE;

        float sacc[8][4];
#pragma unroll
        for (int nt = 0; nt < 8; nt++)
#pragma unroll
            for (int j = 0; j < 4; j++) sacc[nt][j] = 0.f;

#pragma unroll
        for (int k16 = 0; k16 < 4; k16++) {
            uint32_t bh[4][4], bl[4][4];
#pragma unroll
            for (int p = 0; p < 4; p++) {
                uint32_t adr = sKh + ((p * 16 + lr) * FATR + k16 * 16 + lc * 8) * 2;
                LDSM4(bh[p][0], bh[p][1], bh[p][2], bh[p][3], adr);
                adr = sKl + ((p * 16 + lr) * FATR + k16 * 16 + lc * 8) * 2;
                LDSM4(bl[p][0], bl[p][1], bl[p][2], bl[p][3], adr);
            }
#pragma unroll
            for (int nt = 0; nt < 8; nt++) {
                int p = nt >> 1, w = nt & 1;
                MMA16816(sacc[nt], aQh[k16], bh[p][w], bh[p][w + 2]);
                MMA16816(sacc[nt], aQh[k16], bl[p][w], bl[p][w + 2]);
                MMA16816(sacc[nt], aQl[k16], bh[p][w], bh[p][w + 2]);
            }
        }

        if (kb == qb) {
#pragma unroll
            for (int nt = 0; nt < 8; nt++) {
                int c0 = nt * 8 + ec;
                sacc[nt][0] = (c0     <= wm + er)     ? sacc[nt][0] * 0.125f : -INFINITY;
                sacc[nt][1] = (c0 + 1 <= wm + er)     ? sacc[nt][1] * 0.125f : -INFINITY;
                sacc[nt][2] = (c0     <= wm + er + 8) ? sacc[nt][2] * 0.125f : -INFINITY;
                sacc[nt][3] = (c0 + 1 <= wm + er + 8) ? sacc[nt][3] * 0.125f : -INFINITY;
            }
        } else {
#pragma unroll
            for (int nt = 0; nt < 8; nt++)
#pragma unroll
                for (int j = 0; j < 4; j++) sacc[nt][j] *= 0.125f;
        }

        float mx0 = -INFINITY, mx1 = -INFINITY;
#pragma unroll
        for (int nt = 0; nt < 8; nt++) {
            mx0 = fmaxf(mx0, fmaxf(sacc[nt][0], sacc[nt][1]));
            mx1 = fmaxf(mx1, fmaxf(sacc[nt][2], sacc[nt][3]));
        }
#pragma unroll
        for (int off = 1; off < 4; off <<= 1) {
            mx0 = fmaxf(mx0, __shfl_xor_sync(0xffffffffu, mx0, off));
            mx1 = fmaxf(mx1, __shfl_xor_sync(0xffffffffu, mx1, off));
        }
        float mn0 = fmaxf(mi0, mx0), mn1 = fmaxf(mi1, mx1);
        float sum0 = 0.f, sum1 = 0.f;
#pragma unroll
        for (int nt = 0; nt < 8; nt++) {
            sacc[nt][0] = __expf(sacc[nt][0] - mn0);
            sacc[nt][1] = __expf(sacc[nt][1] - mn0);
            sacc[nt][2] = __expf(sacc[nt][2] - mn1);
            sacc[nt][3] = __expf(sacc[nt][3] - mn1);
            sum0 += sacc[nt][0] + sacc[nt][1];
            sum1 += sacc[nt][2] + sacc[nt][3];
        }
#pragma unroll
        for (int off = 1; off < 4; off <<= 1) {
            sum0 += __shfl_xor_sync(0xffffffffu, sum0, off);
            sum1 += __shfl_xor_sync(0xffffffffu, sum1, off);
        }
        float sc0 = __expf(mi0 - mn0), sc1 = __expf(mi1 - mn1);
        li0 = li0 * sc0 + sum0; li1 = li1 * sc1 + sum1;
        mi0 = mn0; mi1 = mn1;
#pragma unroll
        for (int nt = 0; nt < 8; nt++) {
            oacc[nt][0] *= sc0; oacc[nt][1] *= sc0;
            oacc[nt][2] *= sc1; oacc[nt][3] *= sc1;
        }

#pragma unroll
        for (int k16 = 0; k16 < 4; k16++) {
            uint32_t ph[4], pl[4];
#pragma unroll
            for (int half16 = 0; half16 < 2; half16++) {
                int st = 2 * k16 + half16;
                __half2 h01 = __floats2half2_rn(sacc[st][0], sacc[st][1]);
                float2 f01 = __half22float2(h01);
                __half2 l01 = __floats2half2_rn(sacc[st][0] - f01.x, sacc[st][1] - f01.y);
                __half2 h23 = __floats2half2_rn(sacc[st][2], sacc[st][3]);
                float2 f23 = __half22float2(h23);
                __half2 l23 = __floats2half2_rn(sacc[st][2] - f23.x, sacc[st][3] - f23.y);
                ph[half16 * 2]     = *(uint32_t*)&h01;
                ph[half16 * 2 + 1] = *(uint32_t*)&h23;
                pl[half16 * 2]     = *(uint32_t*)&l01;
                pl[half16 * 2 + 1] = *(uint32_t*)&l23;
            }
            uint32_t bvh[4][4], bvl[4][4];
#pragma unroll
            for (int p = 0; p < 4; p++) {
                uint32_t adr = sVh + ((k16 * 16 + lr) * FATR + p * 16 + lc * 8) * 2;
                LDSM4T(bvh[p][0], bvh[p][1], bvh[p][2], bvh[p][3], adr);
                adr = sVl + ((k16 * 16 + lr) * FATR + p * 16 + lc * 8) * 2;
                LDSM4T(bvl[p][0], bvl[p][1], bvl[p][2], bvl[p][3], adr);
            }
#pragma unroll
            for (int nt = 0; nt < 8; nt++) {
                int p = nt >> 1, w = (nt & 1) * 2;
                MMA16816(oacc[nt], ph, bvh[p][w], bvh[p][w + 1]);
                MMA16816(oacc[nt], ph, bvl[p][w], bvl[p][w + 1]);
                MMA16816(oacc[nt], pl, bvh[p][w], bvh[p][w + 1]);
            }
        }
        __syncthreads();
    }

    float inv0 = 1.0f / li0, inv1 = 1.0f / li1;
    int r0g = qb * 64 + wm + er, r1g = r0g + 8;
#pragma unroll
    for (int nt = 0; nt < 8; nt++) {
        int c = h * 64 + nt * 8 + ec;
        float v0 = oacc[nt][0] * inv0, v1 = oacc[nt][1] * inv0;
        float v2 = oacc[nt][2] * inv1, v3 = oacc[nt][3] * inv1;
        __half2 h0 = __floats2half2_rn(v0, v1);
        float2 f0 = __half22float2(h0);
        __half2 l0 = __floats2half2_rn(v0 - f0.x, v1 - f0.y);
        __half2 h1 = __floats2half2_rn(v2, v3);
        float2 f1 = __half22float2(h1);
        __half2 l1 = __floats2half2_rn(v2 - f1.x, v3 - f1.y);
        *(__half2*)&chi[(size_t)r0g * DMODEL + c] = h0;
        *(__half2*)&clo[(size_t)r0g * DMODEL + c] = l0;
        *(__half2*)&chi[(size_t)r1g * DMODEL + c] = h1;
        *(__half2*)&clo[(size_t)r1g * DMODEL + c] = l1;
    }
}

// -------------------- launch --------------------
extern "C" void kernel_launch(void* const* d_in, const int* in_sizes, int n_in,
                              void* d_out, int out_size) {
    const float* x  = (const float*)d_in[0];
    const float* Wq = (const float*)d_in[1];
    const float* Wk = (const float*)d_in[2];
    const float* Wv = (const float*)d_in[3];
    const float* Wo = (const float*)d_in[4];
    const int* start_pos = (const int*)d_in[5];
    float* out = (float*)d_out;

    float *qp, *kp, *vp;
    cudaGetSymbolAddress((void**)&qp, g_q);
    cudaGetSymbolAddress((void**)&kp, g_k);
    cudaGetSymbolAddress((void**)&vp, g_v);
    __half *xhi, *xlo, *wqhi, *wqlo, *wkhi, *wklo, *wvhi, *wvlo, *wohi, *wolo;
    __half *chi, *clo, *qh, *ql, *kh, *kl, *vh, *vl;
    cudaGetSymbolAddress((void**)&xhi, g_xhi);   cudaGetSymbolAddress((void**)&xlo, g_xlo);
    cudaGetSymbolAddress((void**)&wqhi, g_wqhi); cudaGetSymbolAddress((void**)&wqlo, g_wqlo);
    cudaGetSymbolAddress((void**)&wkhi, g_wkhi); cudaGetSymbolAddress((void**)&wklo, g_wklo);
    cudaGetSymbolAddress((void**)&wvhi, g_wvhi); cudaGetSymbolAddress((void**)&wvlo, g_wvlo);
    cudaGetSymbolAddress((void**)&wohi, g_wohi); cudaGetSymbolAddress((void**)&wolo, g_wolo);
    cudaGetSymbolAddress((void**)&chi, g_chi);   cudaGetSymbolAddress((void**)&clo, g_clo);
    cudaGetSymbolAddress((void**)&qh, g_qh);     cudaGetSymbolAddress((void**)&ql, g_ql);
    cudaGetSymbolAddress((void**)&kh, g_kh);     cudaGetSymbolAddress((void**)&kl, g_kl);
    cudaGetSymbolAddress((void**)&vh, g_vh);     cudaGetSymbolAddress((void**)&vl, g_vl);

    cudaFuncSetAttribute(gemm3, cudaFuncAttributeMaxDynamicSharedMemorySize, GSMEM);
    cudaFuncSetAttribute(flash_hmma, cudaFuncAttributeMaxDynamicSharedMemorySize,
                         FLASH_SMEM);

    // 0: all weight splits in one launch
    split_w_kernel<<<(2*WQ4 + 2*WK4) / 256, 256>>>(Wq, Wk, Wv, Wo,
        wqhi, wqlo, wkhi, wklo, wvhi, wvlo, wohi, wolo);
    // 1: x split
    split_kernel<<<(SEQ*DMODEL/4) / 256, 256>>>(x, xhi, xlo, SEQ*DMODEL/4);
    // 2: rope tables
    rope_table_kernel<<<(SEQ * 32 + 255) / 256, 256>>>(start_pos);
    // 3: fused Q/K/V projection (target of ncu sampling)
    gemm3<<<dim3(24, SEQ/128), 256, GSMEM>>>(
        xhi, xlo,
        wqhi, wqlo, qp, DMODEL, 16,
        wkhi, wklo, kp, KVD, 4,
        wvhi, wvlo, vp, KVD,
        DMODEL);
    // 4,5: rope + split q/k
    rope_split_kernel<<<(SEQ * NH  * 32) / 256, 256>>>(qp, qh, ql, NH);
    rope_split_kernel<<<(SEQ * NKV * 32) / 256, 256>>>(kp, kh, kl, NKV);
    // 6: v split
    split_kernel<<<(SEQ*KVD/4) / 256, 256>>>(vp, vh, vl, SEQ*KVD/4);
    // 7: flash attention -> ctx hi/lo
    flash_hmma<<<dim3(NH, SEQ / 64), 128, FLASH_SMEM>>>(qh, ql, kh, kl, vh, vl, chi, clo);
    // 8: O projection
    gemm3<<<dim3(16, SEQ/128), 256, GSMEM>>>(
        chi, clo,
        wohi, wolo, out, DMODEL, 16,
        wohi, wolo, out, DMODEL, 0,
        wohi, wolo, out, DMODEL,
        DMODEL);
}

// round 6
// speedup vs baseline: 3.1196x; 1.0174x over previous
#include <cuda_runtime.h>
#include <cuda_fp16.h>
#include <math.h>
#include <stdint.h>

#define SEQ    2048
#define DMODEL 2048
#define NH     32
#define NKV    8
#define HD     64
#define KVD    (NKV*HD)   // 512

// -------------------- scratch (no allocs allowed) --------------------
__device__ float g_q[SEQ*DMODEL];
__device__ float g_k[SEQ*KVD];
__device__ float g_v[SEQ*KVD];
__device__ float g_cos[SEQ*(HD/2)];
__device__ float g_sin[SEQ*(HD/2)];

// fp16 split buffers (hi/lo)
__device__ __half g_xhi[SEQ*DMODEL],     g_xlo[SEQ*DMODEL];
__device__ __half g_wqhi[DMODEL*DMODEL], g_wqlo[DMODEL*DMODEL];
__device__ __half g_wkhi[KVD*DMODEL],    g_wklo[KVD*DMODEL];
__device__ __half g_wvhi[KVD*DMODEL],    g_wvlo[KVD*DMODEL];
__device__ __half g_wohi[DMODEL*DMODEL], g_wolo[DMODEL*DMODEL];
__device__ __half g_chi[SEQ*DMODEL],     g_clo[SEQ*DMODEL];
__device__ __half g_qh[SEQ*DMODEL],      g_ql[SEQ*DMODEL];
__device__ __half g_kh[SEQ*KVD],         g_kl[SEQ*KVD];
__device__ __half g_vh[SEQ*KVD],         g_vl[SEQ*KVD];

// ==================== helpers ====================
__device__ __forceinline__ uint32_t smem_u32(const void* p) {
    uint32_t a;
    asm("{ .reg .u64 t; cvta.to.shared.u64 t, %1; cvt.u32.u64 %0, t; }"
        : "=r"(a) : "l"(p));
    return a;
}

#define CP_ASYNC16(dst, src) \
    asm volatile("cp.async.cg.shared.global [%0], [%1], 16;" :: "r"(dst), "l"(src) : "memory")
#define CP_COMMIT() asm volatile("cp.async.commit_group;" ::: "memory")
#define CP_WAIT_0() asm volatile("cp.async.wait_group 0;" ::: "memory")

#define LDSM4(r0, r1, r2, r3, addr) \
    asm volatile("ldmatrix.sync.aligned.m8n8.x4.shared.b16 {%0,%1,%2,%3}, [%4];" \
        : "=r"(r0), "=r"(r1), "=r"(r2), "=r"(r3) : "r"(addr))

#define LDSM4T(r0, r1, r2, r3, addr) \
    asm volatile("ldmatrix.sync.aligned.m8n8.x4.trans.shared.b16 {%0,%1,%2,%3}, [%4];" \
        : "=r"(r0), "=r"(r1), "=r"(r2), "=r"(r3) : "r"(addr))

#define MMA16816(d, a, b0, b1) \
    asm volatile("mma.sync.aligned.m16n8k16.row.col.f32.f16.f16.f32 " \
        "{%0,%1,%2,%3}, {%4,%5,%6,%7}, {%8,%9}, {%0,%1,%2,%3};" \
        : "+f"((d)[0]), "+f"((d)[1]), "+f"((d)[2]), "+f"((d)[3]) \
        : "r"((a)[0]), "r"((a)[1]), "r"((a)[2]), "r"((a)[3]), "r"(b0), "r"(b1))

// ==================== fp32 -> fp16 hi/lo split ====================
__device__ __forceinline__ void split4(const float* __restrict__ src,
                                       __half* __restrict__ hi,
                                       __half* __restrict__ lo, int i) {
    float4 x = ((const float4*)src)[i];
    __half h0 = __float2half_rn(x.x), h1 = __float2half_rn(x.y);
    __half h2 = __float2half_rn(x.z), h3 = __float2half_rn(x.w);
    __half2* hp = (__half2*)(hi + i * 4);
    __half2* lp = (__half2*)(lo + i * 4);
    hp[0] = __half2(h0, h1);
    hp[1] = __half2(h2, h3);
    lp[0] = __half2(__float2half_rn(x.x - __half2float(h0)),
                    __float2half_rn(x.y - __half2float(h1)));
    lp[1] = __half2(__float2half_rn(x.z - __half2float(h2)),
                    __float2half_rn(x.w - __half2float(h3)));
}

__global__ void split_kernel(const float* __restrict__ src,
                             __half* __restrict__ hi,
                             __half* __restrict__ lo, int n4) {
    int i = blockIdx.x * blockDim.x + threadIdx.x;
    if (i < n4) split4(src, hi, lo, i);
}

#define WQ4 (DMODEL*DMODEL/4)
#define WK4 (KVD*DMODEL/4)
__global__ void split_w_kernel(const float* __restrict__ Wq, const float* __restrict__ Wk,
                               const float* __restrict__ Wv, const float* __restrict__ Wo,
                               __half* __restrict__ qh, __half* __restrict__ ql,
                               __half* __restrict__ kh, __half* __restrict__ kl,
                               __half* __restrict__ vh, __half* __restrict__ vl,
                               __half* __restrict__ oh, __half* __restrict__ ol) {
    int i = blockIdx.x * blockDim.x + threadIdx.x;
    if (i < WQ4)                      split4(Wq, qh, ql, i);
    else if (i < WQ4 + WK4)           split4(Wk, kh, kl, i - WQ4);
    else if (i < WQ4 + 2*WK4)         split4(Wv, vh, vl, i - WQ4 - WK4);
    else if (i < 2*WQ4 + 2*WK4)       split4(Wo, oh, ol, i - WQ4 - 2*WK4);
}

// ==================== HMMA fp16x3 GEMM (projections) ====================
#define BK 32
#define ASTRH 40
#define TILEB (128 * ASTRH * 2)     // 10240 bytes
#define GSMEM (TILEB * 8)           // 2 stages x 4 tiles = 81920

__global__ void __launch_bounds__(256, 2) gemm3(
    const __half* __restrict__ Ahi, const __half* __restrict__ Alo,
    const __half* __restrict__ B0h, const __half* __restrict__ B0l,
    float* __restrict__ C0, int N0, int nx0,
    const __half* __restrict__ B1h, const __half* __restrict__ B1l,
    float* __restrict__ C1, int N1, int nx1,
    const __half* __restrict__ B2h, const __half* __restrict__ B2l,
    float* __restrict__ C2, int N2,
    int K) {
    extern __shared__ __half gsm[];
    const int bx = blockIdx.x;
    const __half *Bh, *Bl; float* C; int Nc, bnl;
    if (bx < nx0)            { Bh = B0h; Bl = B0l; C = C0; Nc = N0; bnl = bx * 128; }
    else if (bx < nx0 + nx1) { Bh = B1h; Bl = B1l; C = C1; Nc = N1; bnl = (bx - nx0) * 128; }
    else                     { Bh = B2h; Bl = B2l; C = C2; Nc = N2; bnl = (bx - nx0 - nx1) * 128; }

    const int tid = threadIdx.x;
    const int wid = tid >> 5, lane = tid & 31;
    const int wm = (wid & 1) * 64;
    const int wn = (wid >> 1) * 32;
    const int bm = blockIdx.y * 128;
    const int lr = lane & 15, lc = lane >> 4;

    uint32_t sbu = smem_u32(gsm);
    const int r0_ = tid >> 2, r1_ = r0_ + 64;
    const int pp = (tid & 3) * 8;

    float acc[4][4][4];
#pragma unroll
    for (int a = 0; a < 4; a++)
#pragma unroll
        for (int b = 0; b < 4; b++)
#pragma unroll
            for (int c = 0; c < 4; c++) acc[a][b][c] = 0.f;

#define LOADCHUNK(st, k0) do {                                                  \
    uint32_t _b = sbu + (st) * (4 * TILEB);                                     \
    CP_ASYNC16(_b + (r0_ * ASTRH + pp) * 2,                                     \
               Ahi + (size_t)(bm + r0_) * K + (k0) + pp);                       \
    CP_ASYNC16(_b + (r1_ * ASTRH + pp) * 2,                                     \
               Ahi + (size_t)(bm + r1_) * K + (k0) + pp);                       \
    CP_ASYNC16(_b + TILEB + (r0_ * ASTRH + pp) * 2,                             \
               Alo + (size_t)(bm + r0_) * K + (k0) + pp);                       \
    CP_ASYNC16(_b + TILEB + (r1_ * ASTRH + pp) * 2,                             \
               Alo + (size_t)(bm + r1_) * K + (k0) + pp);                       \
    CP_ASYNC16(_b + 2 * TILEB + (r0_ * ASTRH + pp) * 2,                         \
               Bh + (size_t)(bnl + r0_) * K + (k0) + pp);                       \
    CP_ASYNC16(_b + 2 * TILEB + (r1_ * ASTRH + pp) * 2,                         \
               Bh + (size_t)(bnl + r1_) * K + (k0) + pp);                       \
    CP_ASYNC16(_b + 3 * TILEB + (r0_ * ASTRH + pp) * 2,                         \
               Bl + (size_t)(bnl + r0_) * K + (k0) + pp);                       \
    CP_ASYNC16(_b + 3 * TILEB + (r1_ * ASTRH + pp) * 2,                         \
               Bl + (size_t)(bnl + r1_) * K + (k0) + pp);                       \
} while (0)

    const int kiters = K / BK;
    LOADCHUNK(0, 0);
    CP_COMMIT();

    for (int i = 0; i < kiters; i++) {
        int s = i & 1;
        // wait for chunk i, single barrier, then immediately overlap chunk i+1 load
        CP_WAIT_0();
        __syncthreads();
        if (i + 1 < kiters) {
            LOADCHUNK(s ^ 1, (i + 1) * BK);
            CP_COMMIT();
        }

        uint32_t base = sbu + s * (4 * TILEB);
#pragma unroll
        for (int k16 = 0; k16 < 2; k16++) {
            int koff = k16 * 16 + lc * 8;
            uint32_t aH[4][4], aL[4][4], bH[2][4], bL[2][4];
#pragma unroll
            for (int mt = 0; mt < 4; mt++) {
                uint32_t adr = base + ((wm + mt * 16 + lr) * ASTRH + koff) * 2;
                LDSM4(aH[mt][0], aH[mt][1], aH[mt][2], aH[mt][3], adr);
            }
#pragma unroll
            for (int p = 0; p < 2; p++) {
                uint32_t adr = base + 2 * TILEB + ((wn + p * 16 + lr) * ASTRH + koff) * 2;
                LDSM4(bH[p][0], bH[p][1], bH[p][2], bH[p][3], adr);
            }
#pragma unroll
            for (int mt = 0; mt < 4; mt++)
#pragma unroll
                for (int nt = 0; nt < 4; nt++) {
                    int p = nt >> 1, w = nt & 1;
                    MMA16816(acc[mt][nt], aH[mt], bH[p][w], bH[p][w + 2]);
                }
#pragma unroll
            for (int p = 0; p < 2; p++) {
                uint32_t adr = base + 3 * TILEB + ((wn + p * 16 + lr) * ASTRH + koff) * 2;
                LDSM4(bL[p][0], bL[p][1], bL[p][2], bL[p][3], adr);
            }
#pragma unroll
            for (int mt = 0; mt < 4; mt++)
#pragma unroll
                for (int nt = 0; nt < 4; nt++) {
                    int p = nt >> 1, w = nt & 1;
                    MMA16816(acc[mt][nt], aH[mt], bL[p][w], bL[p][w + 2]);
                }
#pragma unroll
            for (int mt = 0; mt < 4; mt++) {
                uint32_t adr = base + TILEB + ((wm + mt * 16 + lr) * ASTRH + koff) * 2;
                LDSM4(aL[mt][0], aL[mt][1], aL[mt][2], aL[mt][3], adr);
            }
#pragma unroll
            for (int mt = 0; mt < 4; mt++)
#pragma unroll
                for (int nt = 0; nt < 4; nt++) {
                    int p = nt >> 1, w = nt & 1;
                    MMA16816(acc[mt][nt], aL[mt], bH[p][w], bH[p][w + 2]);
                }
        }
    }

    int er = lane >> 2, ec = (lane & 3) * 2;
#pragma unroll
    for (int mt = 0; mt < 4; mt++) {
#pragma unroll
        for (int nt = 0; nt < 4; nt++) {
            int r = bm + wm + mt * 16 + er;
            int c = bnl + wn + nt * 8 + ec;
            *(float2*)&C[(size_t)r * Nc + c]       = make_float2(acc[mt][nt][0], acc[mt][nt][1]);
            *(float2*)&C[(size_t)(r + 8) * Nc + c] = make_float2(acc[mt][nt][2], acc[mt][nt][3]);
        }
    }
}

// -------------------- RoPE --------------------
__global__ void rope_table_kernel(const int* __restrict__ start_pos) {
    int idx = blockIdx.x * blockDim.x + threadIdx.x;
    if (idx >= SEQ * 32) return;
    int t = idx >> 5, j = idx & 31;
    const double PI = 3.14159265358979323846;
    double e = (double)(2 * j) / 64.0;
    double invf = pow(500000.0, -e);
    double wavelen = 2.0 * PI / invf;
    double inv;
    if (wavelen > 8192.0) {
        inv = invf / 32.0;
    } else if (wavelen < 2048.0) {
        inv = invf;
    } else {
        double smooth = (8192.0 / wavelen - 1.0) / 3.0;
        inv = (1.0 - smooth) * (invf / 32.0) + smooth * invf;
    }
    float angle = (float)(start_pos[0] + t) * (float)inv;
    g_cos[idx] = (float)cos((double)angle);
    g_sin[idx] = (float)sin((double)angle);
}

// fused RoPE + fp16 hi/lo split, q and k in one launch
__global__ void rope_split_qk_kernel(const float* __restrict__ qbuf,
                                     const float* __restrict__ kbuf,
                                     __half* __restrict__ qhi, __half* __restrict__ qlo,
                                     __half* __restrict__ khi, __half* __restrict__ klo) {
    int idx = blockIdx.x * blockDim.x + threadIdx.x;
    // combined domain: t x 40 heads x 32 dims (32 q heads then 8 k heads)
    if (idx >= SEQ * 40 * 32) return;
    int j = idx & 31;
    int hh = (idx >> 5) % 40;
    int t = idx / (32 * 40);
    float c = g_cos[t * 32 + j];
    float s = g_sin[t * 32 + j];
    const float* buf; __half *hi, *lo; size_t off;
    if (hh < NH) {
        buf = qbuf; hi = qhi; lo = qlo;
        off = (size_t)t * DMODEL + hh * 64 + j;
    } else {
        buf = kbuf; hi = khi; lo = klo;
        off = (size_t)t * KVD + (hh - NH) * 64 + j;
    }
    const float* p = buf + off;
    float x1 = p[0], x2 = p[32];
    float y1 = x1 * c - x2 * s;
    float y2 = x2 * c + x1 * s;
    __half h1 = __float2half_rn(y1), h2 = __float2half_rn(y2);
    hi[off]      = h1;
    hi[off + 32] = h2;
    lo[off]      = __float2half_rn(y1 - __half2float(h1));
    lo[off + 32] = __float2half_rn(y2 - __half2float(h2));
}

// ==================== HMMA flash attention ====================
#define FATR 72
#define FTILE (64 * FATR * 2)
#define FLASH_SMEM (FTILE * 10)

__global__ void __launch_bounds__(128) flash_hmma(
    const __half* __restrict__ qhi, const __half* __restrict__ qlo,
    const __half* __restrict__ khi, const __half* __restrict__ klo,
    const __half* __restrict__ vhi, const __half* __restrict__ vlo,
    __half* __restrict__ chi, __half* __restrict__ clo) {
    extern __shared__ __half fsm[];
    const int h  = blockIdx.x;
    const int qb = gridDim.y - 1 - blockIdx.y;
    const int g  = h >> 2;
    const int tid = threadIdx.x;
    const int wid = tid >> 5, lane = tid & 31;
    const int wm = wid * 16;
    const int er = lane >> 2, ec = (lane & 3) * 2;
    const int lr = lane & 15, lc = lane >> 4;

    uint32_t sb = smem_u32(fsm);
    uint32_t sQh = sb, sQl = sb + FTILE;

#pragma unroll
    for (int l = 0; l < 4; l++) {
        int c = tid + l * 128;
        int row = c >> 3, cc = c & 7;
        size_t off = (size_t)(qb * 64 + row) * DMODEL + h * 64 + cc * 8;
        CP_ASYNC16(sQh + row * FATR * 2 + cc * 16, qhi + off);
        CP_ASYNC16(sQl + row * FATR * 2 + cc * 16, qlo + off);
    }
#define KV_LOAD(kb_, st_) do {                                                  \
    uint32_t base = sb + 2 * FTILE + (st_) * 4 * FTILE;                         \
    _Pragma("unroll")                                                           \
    for (int l = 0; l < 4; l++) {                                               \
        int c = tid + l * 128;                                                  \
        int row = c >> 3, cc = c & 7;                                           \
        size_t off = (size_t)((kb_) * 64 + row) * KVD + g * 64 + cc * 8;        \
        uint32_t d = row * FATR * 2 + cc * 16;                                  \
        CP_ASYNC16(base + 0 * FTILE + d, khi + off);                            \
        CP_ASYNC16(base + 1 * FTILE + d, klo + off);                            \
        CP_ASYNC16(base + 2 * FTILE + d, vhi + off);                            \
        CP_ASYNC16(base + 3 * FTILE + d, vlo + off);                            \
    }                                                                           \
} while (0)

    KV_LOAD(0, 0);
    CP_COMMIT();

    uint32_t aQh[4][4], aQl[4][4];
    float oacc[8][4];
    float mi0 = -INFINITY, mi1 = -INFINITY, li0 = 0.f, li1 = 0.f;
#pragma unroll
    for (int nt = 0; nt < 8; nt++)
#pragma unroll
        for (int j = 0; j < 4; j++) oacc[nt][j] = 0.f;

    for (int kb = 0; kb <= qb; kb++) {
        int stage = kb & 1;
        // single barrier per block; overlap next KV load with compute
        CP_WAIT_0();
        __syncthreads();
        if (kb < qb) {
            KV_LOAD(kb + 1, stage ^ 1);
            CP_COMMIT();
        }

        if (kb == 0) {
#pragma unroll
            for (int k16 = 0; k16 < 4; k16++) {
                uint32_t ah = sQh + ((wm + lr) * FATR + k16 * 16 + lc * 8) * 2;
                LDSM4(aQh[k16][0], aQh[k16][1], aQh[k16][2], aQh[k16][3], ah);
                uint32_t al = sQl + ((wm + lr) * FATR + k16 * 16 + lc * 8) * 2;
                LDSM4(aQl[k16][0], aQl[k16][1], aQl[k16][2], aQl[k16][3], al);
            }
        }

        uint32_t base = sb + 2 * FTILE + stage * 4 * FTILE;
        uint32_t sKh = base, sKl = base + FTILE;
        uint32_t sVh = base + 2 * FTILE, sVl = base + 3 * FTILE;

        float sacc[8][4];
#pragma unroll
        for (int nt = 0; nt < 8; nt++)
#pragma unroll
            for (int j = 0; j < 4; j++) sacc[nt][j] = 0.f;

#pragma unroll
        for (int k16 = 0; k16 < 4; k16++) {
            uint32_t bh[4][4], bl[4][4];
#pragma unroll
            for (int p = 0; p < 4; p++) {
                uint32_t adr = sKh + ((p * 16 + lr) * FATR + k16 * 16 + lc * 8) * 2;
                LDSM4(bh[p][0], bh[p][1], bh[p][2], bh[p][3], adr);
                adr = sKl + ((p * 16 + lr) * FATR + k16 * 16 + lc * 8) * 2;
                LDSM4(bl[p][0], bl[p][1], bl[p][2], bl[p][3], adr);
            }
#pragma unroll
            for (int nt = 0; nt < 8; nt++) {
                int p = nt >> 1, w = nt & 1;
                MMA16816(sacc[nt], aQh[k16], bh[p][w], bh[p][w + 2]);
                MMA16816(sacc[nt], aQh[k16], bl[p][w], bl[p][w + 2]);
                MMA16816(sacc[nt], aQl[k16], bh[p][w], bh[p][w + 2]);
            }
        }

        if (kb == qb) {
#pragma unroll
            for (int nt = 0; nt < 8; nt++) {
                int c0 = nt * 8 + ec;
                sacc[nt][0] = (c0     <= wm + er)     ? sacc[nt][0] * 0.125f : -INFINITY;
                sacc[nt][1] = (c0 + 1 <= wm + er)     ? sacc[nt][1] * 0.125f : -INFINITY;
                sacc[nt][2] = (c0     <= wm + er + 8) ? sacc[nt][2] * 0.125f : -INFINITY;
                sacc[nt][3] = (c0 + 1 <= wm + er + 8) ? sacc[nt][3] * 0.125f : -INFINITY;
            }
        } else {
#pragma unroll
            for (int nt = 0; nt < 8; nt++)
#pragma unroll
                for (int j = 0; j < 4; j++) sacc[nt][j] *= 0.125f;
        }

        float mx0 = -INFINITY, mx1 = -INFINITY;
#pragma unroll
        for (int nt = 0; nt < 8; nt++) {
            mx0 = fmaxf(mx0, fmaxf(sacc[nt][0], sacc[nt][1]));
            mx1 = fmaxf(mx1, fmaxf(sacc[nt][2], sacc[nt][3]));
        }
#pragma unroll
        for (int off = 1; off < 4; off <<= 1) {
            mx0 = fmaxf(mx0, __shfl_xor_sync(0xffffffffu, mx0, off));
            mx1 = fmaxf(mx1, __shfl_xor_sync(0xffffffffu, mx1, off));
        }
        float mn0 = fmaxf(mi0, mx0), mn1 = fmaxf(mi1, mx1);
        float sum0 = 0.f, sum1 = 0.f;
#pragma unroll
        for (int nt = 0; nt < 8; nt++) {
            sacc[nt][0] = __expf(sacc[nt][0] - mn0);
            sacc[nt][1] = __expf(sacc[nt][1] - mn0);
            sacc[nt][2] = __expf(sacc[nt][2] - mn1);
            sacc[nt][3] = __expf(sacc[nt][3] - mn1);
            sum0 += sacc[nt][0] + sacc[nt][1];
            sum1 += sacc[nt][2] + sacc[nt][3];
        }
#pragma unroll
        for (int off = 1; off < 4; off <<= 1) {
            sum0 += __shfl_xor_sync(0xffffffffu, sum0, off);
            sum1 += __shfl_xor_sync(0xffffffffu, sum1, off);
        }
        float sc0 = __expf(mi0 - mn0), sc1 = __expf(mi1 - mn1);
        li0 = li0 * sc0 + sum0; li1 = li1 * sc1 + sum1;
        mi0 = mn0; mi1 = mn1;
#pragma unroll
        for (int nt = 0; nt < 8; nt++) {
            oacc[nt][0] *= sc0; oacc[nt][1] *= sc0;
            oacc[nt][2] *= sc1; oacc[nt][3] *= sc1;
        }

#pragma unroll
        for (int k16 = 0; k16 < 4; k16++) {
            uint32_t ph[4], pl[4];
#pragma unroll
            for (int half16 = 0; half16 < 2; half16++) {
                int st = 2 * k16 + half16;
                __half2 h01 = __floats2half2_rn(sacc[st][0], sacc[st][1]);
                float2 f01 = __half22float2(h01);
                __half2 l01 = __floats2half2_rn(sacc[st][0] - f01.x, sacc[st][1] - f01.y);
                __half2 h23 = __floats2half2_rn(sacc[st][2], sacc[st][3]);
                float2 f23 = __half22float2(h23);
                __half2 l23 = __floats2half2_rn(sacc[st][2] - f23.x, sacc[st][3] - f23.y);
                ph[half16 * 2]     = *(uint32_t*)&h01;
                ph[half16 * 2 + 1] = *(uint32_t*)&h23;
                pl[half16 * 2]     = *(uint32_t*)&l01;
                pl[half16 * 2 + 1] = *(uint32_t*)&l23;
            }
            uint32_t bvh[4][4], bvl[4][4];
#pragma unroll
            for (int p = 0; p < 4; p++) {
                uint32_t adr = sVh + ((k16 * 16 + lr) * FATR + p * 16 + lc * 8) * 2;
                LDSM4T(bvh[p][0], bvh[p][1], bvh[p][2], bvh[p][3], adr);
                adr = sVl + ((k16 * 16 + lr) * FATR + p * 16 + lc * 8) * 2;
                LDSM4T(bvl[p][0], bvl[p][1], bvl[p][2], bvl[p][3], adr);
            }
#pragma unroll
            for (int nt = 0; nt < 8; nt++) {
                int p = nt >> 1, w = (nt & 1) * 2;
                MMA16816(oacc[nt], ph, bvh[p][w], bvh[p][w + 1]);
                MMA16816(oacc[nt], ph, bvl[p][w], bvl[p][w + 1]);
                MMA16816(oacc[nt], pl, bvh[p][w], bvh[p][w + 1]);
            }
        }
    }

    float inv0 = 1.0f / li0, inv1 = 1.0f / li1;
    int r0g = qb * 64 + wm + er, r1g = r0g + 8;
#pragma unroll
    for (int nt = 0; nt < 8; nt++) {
        int c = h * 64 + nt * 8 + ec;
        float v0 = oacc[nt][0] * inv0, v1 = oacc[nt][1] * inv0;
        float v2 = oacc[nt][2] * inv1, v3 = oacc[nt][3] * inv1;
        __half2 h0 = __floats2half2_rn(v0, v1);
        float2 f0 = __half22float2(h0);
        __half2 l0 = __floats2half2_rn(v0 - f0.x, v1 - f0.y);
        __half2 h1 = __floats2half2_rn(v2, v3);
        float2 f1 = __half22float2(h1);
        __half2 l1 = __floats2half2_rn(v2 - f1.x, v3 - f1.y);
        *(__half2*)&chi[(size_t)r0g * DMODEL + c] = h0;
        *(__half2*)&clo[(size_t)r0g * DMODEL + c] = l0;
        *(__half2*)&chi[(size_t)r1g * DMODEL + c] = h1;
        *(__half2*)&clo[(size_t)r1g * DMODEL + c] = l1;
    }
}

// -------------------- launch --------------------
extern "C" void kernel_launch(void* const* d_in, const int* in_sizes, int n_in,
                              void* d_out, int out_size) {
    const float* x  = (const float*)d_in[0];
    const float* Wq = (const float*)d_in[1];
    const float* Wk = (const float*)d_in[2];
    const float* Wv = (const float*)d_in[3];
    const float* Wo = (const float*)d_in[4];
    const int* start_pos = (const int*)d_in[5];
    float* out = (float*)d_out;

    float *qp, *kp, *vp;
    cudaGetSymbolAddress((void**)&qp, g_q);
    cudaGetSymbolAddress((void**)&kp, g_k);
    cudaGetSymbolAddress((void**)&vp, g_v);
    __half *xhi, *xlo, *wqhi, *wqlo, *wkhi, *wklo, *wvhi, *wvlo, *wohi, *wolo;
    __half *chi, *clo, *qh, *ql, *kh, *kl, *vh, *vl;
    cudaGetSymbolAddress((void**)&xhi, g_xhi);   cudaGetSymbolAddress((void**)&xlo, g_xlo);
    cudaGetSymbolAddress((void**)&wqhi, g_wqhi); cudaGetSymbolAddress((void**)&wqlo, g_wqlo);
    cudaGetSymbolAddress((void**)&wkhi, g_wkhi); cudaGetSymbolAddress((void**)&wklo, g_wklo);
    cudaGetSymbolAddress((void**)&wvhi, g_wvhi); cudaGetSymbolAddress((void**)&wvlo, g_wvlo);
    cudaGetSymbolAddress((void**)&wohi, g_wohi); cudaGetSymbolAddress((void**)&wolo, g_wolo);
    cudaGetSymbolAddress((void**)&chi, g_chi);   cudaGetSymbolAddress((void**)&clo, g_clo);
    cudaGetSymbolAddress((void**)&qh, g_qh);     cudaGetSymbolAddress((void**)&ql, g_ql);
    cudaGetSymbolAddress((void**)&kh, g_kh);     cudaGetSymbolAddress((void**)&kl, g_kl);
    cudaGetSymbolAddress((void**)&vh, g_vh);     cudaGetSymbolAddress((void**)&vl, g_vl);

    cudaFuncSetAttribute(gemm3, cudaFuncAttributeMaxDynamicSharedMemorySize, GSMEM);
    cudaFuncSetAttribute(flash_hmma, cudaFuncAttributeMaxDynamicSharedMemorySize,
                         FLASH_SMEM);

    split_w_kernel<<<(2*WQ4 + 2*WK4) / 256, 256>>>(Wq, Wk, Wv, Wo,
        wqhi, wqlo, wkhi, wklo, wvhi, wvlo, wohi, wolo);
    split_kernel<<<(SEQ*DMODEL/4) / 256, 256>>>(x, xhi, xlo, SEQ*DMODEL/4);
    rope_table_kernel<<<(SEQ * 32 + 255) / 256, 256>>>(start_pos);
    // fused Q/K/V projection (ncu sampling target at launch index 3)
    gemm3<<<dim3(24, SEQ/128), 256, GSMEM>>>(
        xhi, xlo,
        wqhi, wqlo, qp, DMODEL, 16,
        wkhi, wklo, kp, KVD, 4,
        wvhi, wvlo, vp, KVD,
        DMODEL);
    rope_split_qk_kernel<<<(SEQ * 40 * 32) / 256, 256>>>(qp, kp, qh, ql, kh, kl);
    split_kernel<<<(SEQ*KVD/4) / 256, 256>>>(vp, vh, vl, SEQ*KVD/4);
    flash_hmma<<<dim3(NH, SEQ / 64), 128, FLASH_SMEM>>>(qh, ql, kh, kl, vh, vl, chi, clo);
    gemm3<<<dim3(16, SEQ/128), 256, GSMEM>>>(
        chi, clo,
        wohi, wolo, out, DMODEL, 16,
        wohi, wolo, out, DMODEL, 0,
        wohi, wolo, out, DMODEL,
        DMODEL);
}

// round 7
// speedup vs baseline: 3.1283x; 1.0028x over previous
#include <cuda_runtime.h>
#include <cuda_fp16.h>
#include <math.h>
#include <stdint.h>

#define SEQ    2048
#define DMODEL 2048
#define NH     32
#define NKV    8
#define HD     64
#define KVD    (NKV*HD)   // 512

// -------------------- scratch (no allocs allowed) --------------------
__device__ float g_q[SEQ*DMODEL],  g_q2[SEQ*DMODEL];
__device__ float g_k[SEQ*KVD],     g_k2[SEQ*KVD];
__device__ float g_v[SEQ*KVD],     g_v2[SEQ*KVD];
__device__ float g_cos[SEQ*(HD/2)];
__device__ float g_sin[SEQ*(HD/2)];

// fp16 split buffers (hi/lo)
__device__ __half g_xhi[SEQ*DMODEL],     g_xlo[SEQ*DMODEL];
__device__ __half g_wqhi[DMODEL*DMODEL], g_wqlo[DMODEL*DMODEL];
__device__ __half g_wkhi[KVD*DMODEL],    g_wklo[KVD*DMODEL];
__device__ __half g_wvhi[KVD*DMODEL],    g_wvlo[KVD*DMODEL];
__device__ __half g_wohi[DMODEL*DMODEL], g_wolo[DMODEL*DMODEL];
__device__ __half g_chi[SEQ*DMODEL],     g_clo[SEQ*DMODEL];
__device__ __half g_qh[SEQ*DMODEL],      g_ql[SEQ*DMODEL];
__device__ __half g_kh[SEQ*KVD],         g_kl[SEQ*KVD];
__device__ __half g_vh[SEQ*KVD],         g_vl[SEQ*KVD];

// ==================== helpers ====================
__device__ __forceinline__ uint32_t smem_u32(const void* p) {
    uint32_t a;
    asm("{ .reg .u64 t; cvta.to.shared.u64 t, %1; cvt.u32.u64 %0, t; }"
        : "=r"(a) : "l"(p));
    return a;
}

#define CP_ASYNC16(dst, src) \
    asm volatile("cp.async.cg.shared.global [%0], [%1], 16;" :: "r"(dst), "l"(src) : "memory")
#define CP_COMMIT() asm volatile("cp.async.commit_group;" ::: "memory")
#define CP_WAIT_0() asm volatile("cp.async.wait_group 0;" ::: "memory")

#define LDSM4(r0, r1, r2, r3, addr) \
    asm volatile("ldmatrix.sync.aligned.m8n8.x4.shared.b16 {%0,%1,%2,%3}, [%4];" \
        : "=r"(r0), "=r"(r1), "=r"(r2), "=r"(r3) : "r"(addr))

#define LDSM4T(r0, r1, r2, r3, addr) \
    asm volatile("ldmatrix.sync.aligned.m8n8.x4.trans.shared.b16 {%0,%1,%2,%3}, [%4];" \
        : "=r"(r0), "=r"(r1), "=r"(r2), "=r"(r3) : "r"(addr))

#define MMA16816(d, a, b0, b1) \
    asm volatile("mma.sync.aligned.m16n8k16.row.col.f32.f16.f16.f32 " \
        "{%0,%1,%2,%3}, {%4,%5,%6,%7}, {%8,%9}, {%0,%1,%2,%3};" \
        : "+f"((d)[0]), "+f"((d)[1]), "+f"((d)[2]), "+f"((d)[3]) \
        : "r"((a)[0]), "r"((a)[1]), "r"((a)[2]), "r"((a)[3]), "r"(b0), "r"(b1))

// ==================== fp32 -> fp16 hi/lo split ====================
__device__ __forceinline__ void split4(const float* __restrict__ src,
                                       __half* __restrict__ hi,
                                       __half* __restrict__ lo, int i) {
    float4 x = ((const float4*)src)[i];
    __half h0 = __float2half_rn(x.x), h1 = __float2half_rn(x.y);
    __half h2 = __float2half_rn(x.z), h3 = __float2half_rn(x.w);
    __half2* hp = (__half2*)(hi + i * 4);
    __half2* lp = (__half2*)(lo + i * 4);
    hp[0] = __half2(h0, h1);
    hp[1] = __half2(h2, h3);
    lp[0] = __half2(__float2half_rn(x.x - __half2float(h0)),
                    __float2half_rn(x.y - __half2float(h1)));
    lp[1] = __half2(__float2half_rn(x.z - __half2float(h2)),
                    __float2half_rn(x.w - __half2float(h3)));
}

__global__ void split_kernel(const float* __restrict__ src,
                             __half* __restrict__ hi,
                             __half* __restrict__ lo, int n4) {
    int i = blockIdx.x * blockDim.x + threadIdx.x;
    if (i < n4) split4(src, hi, lo, i);
}

// add two fp32 partials, then split
__global__ void split_add_kernel(const float* __restrict__ s0,
                                 const float* __restrict__ s1,
                                 __half* __restrict__ hi,
                                 __half* __restrict__ lo, int n4) {
    int i = blockIdx.x * blockDim.x + threadIdx.x;
    if (i >= n4) return;
    float4 a = ((const float4*)s0)[i];
    float4 b = ((const float4*)s1)[i];
    float x0 = a.x + b.x, x1 = a.y + b.y, x2 = a.z + b.z, x3 = a.w + b.w;
    __half h0 = __float2half_rn(x0), h1 = __float2half_rn(x1);
    __half h2 = __float2half_rn(x2), h3 = __float2half_rn(x3);
    __half2* hp = (__half2*)(hi + i * 4);
    __half2* lp = (__half2*)(lo + i * 4);
    hp[0] = __half2(h0, h1);
    hp[1] = __half2(h2, h3);
    lp[0] = __half2(__float2half_rn(x0 - __half2float(h0)),
                    __float2half_rn(x1 - __half2float(h1)));
    lp[1] = __half2(__float2half_rn(x2 - __half2float(h2)),
                    __float2half_rn(x3 - __half2float(h3)));
}

#define WQ4 (DMODEL*DMODEL/4)
#define WK4 (KVD*DMODEL/4)
__global__ void split_w_kernel(const float* __restrict__ Wq, const float* __restrict__ Wk,
                               const float* __restrict__ Wv, const float* __restrict__ Wo,
                               __half* __restrict__ qh, __half* __restrict__ ql,
                               __half* __restrict__ kh, __half* __restrict__ kl,
                               __half* __restrict__ vh, __half* __restrict__ vl,
                               __half* __restrict__ oh, __half* __restrict__ ol) {
    int i = blockIdx.x * blockDim.x + threadIdx.x;
    if (i < WQ4)                      split4(Wq, qh, ql, i);
    else if (i < WQ4 + WK4)           split4(Wk, kh, kl, i - WQ4);
    else if (i < WQ4 + 2*WK4)         split4(Wv, vh, vl, i - WQ4 - WK4);
    else if (i < 2*WQ4 + 2*WK4)       split4(Wo, oh, ol, i - WQ4 - 2*WK4);
}

// ==================== HMMA fp16x3 GEMM (projections) ====================
// Split-K along blockIdx.z: each z computes Khalf columns into its own
// fp32 partial buffer; the partial add is fused into downstream kernels.
#define BK 32
#define ASTRH 40
#define TILEB (128 * ASTRH * 2)     // 10240 bytes
#define GSMEM (TILEB * 8)           // 2 stages x 4 tiles = 81920

__global__ void __launch_bounds__(256, 2) gemm3(
    const __half* __restrict__ Ahi, const __half* __restrict__ Alo,
    const __half* __restrict__ B0h, const __half* __restrict__ B0l,
    float* __restrict__ C0a, float* __restrict__ C0b, int N0, int nx0,
    const __half* __restrict__ B1h, const __half* __restrict__ B1l,
    float* __restrict__ C1a, float* __restrict__ C1b, int N1, int nx1,
    const __half* __restrict__ B2h, const __half* __restrict__ B2l,
    float* __restrict__ C2a, float* __restrict__ C2b, int N2,
    int K, int Khalf) {
    extern __shared__ __half gsm[];
    const int bx = blockIdx.x;
    const int z = blockIdx.z;
    const __half *Bh, *Bl; float* C; int Nc, bnl;
    if (bx < nx0)            { Bh = B0h; Bl = B0l; C = z ? C0b : C0a; Nc = N0; bnl = bx * 128; }
    else if (bx < nx0 + nx1) { Bh = B1h; Bl = B1l; C = z ? C1b : C1a; Nc = N1; bnl = (bx - nx0) * 128; }
    else                     { Bh = B2h; Bl = B2l; C = z ? C2b : C2a; Nc = N2; bnl = (bx - nx0 - nx1) * 128; }
    const int koff = z * Khalf;

    const int tid = threadIdx.x;
    const int wid = tid >> 5, lane = tid & 31;
    const int wm = (wid & 1) * 64;
    const int wn = (wid >> 1) * 32;
    const int bm = blockIdx.y * 128;
    const int lr = lane & 15, lc = lane >> 4;

    uint32_t sbu = smem_u32(gsm);
    const int r0_ = tid >> 2, r1_ = r0_ + 64;
    const int pp = (tid & 3) * 8;

    float acc[4][4][4];
#pragma unroll
    for (int a = 0; a < 4; a++)
#pragma unroll
        for (int b = 0; b < 4; b++)
#pragma unroll
            for (int c = 0; c < 4; c++) acc[a][b][c] = 0.f;

#define LOADCHUNK(st, k0) do {                                                  \
    uint32_t _b = sbu + (st) * (4 * TILEB);                                     \
    CP_ASYNC16(_b + (r0_ * ASTRH + pp) * 2,                                     \
               Ahi + (size_t)(bm + r0_) * K + (k0) + pp);                       \
    CP_ASYNC16(_b + (r1_ * ASTRH + pp) * 2,                                     \
               Ahi + (size_t)(bm + r1_) * K + (k0) + pp);                       \
    CP_ASYNC16(_b + TILEB + (r0_ * ASTRH + pp) * 2,                             \
               Alo + (size_t)(bm + r0_) * K + (k0) + pp);                       \
    CP_ASYNC16(_b + TILEB + (r1_ * ASTRH + pp) * 2,                             \
               Alo + (size_t)(bm + r1_) * K + (k0) + pp);                       \
    CP_ASYNC16(_b + 2 * TILEB + (r0_ * ASTRH + pp) * 2,                         \
               Bh + (size_t)(bnl + r0_) * K + (k0) + pp);                       \
    CP_ASYNC16(_b + 2 * TILEB + (r1_ * ASTRH + pp) * 2,                         \
               Bh + (size_t)(bnl + r1_) * K + (k0) + pp);                       \
    CP_ASYNC16(_b + 3 * TILEB + (r0_ * ASTRH + pp) * 2,                         \
               Bl + (size_t)(bnl + r0_) * K + (k0) + pp);                       \
    CP_ASYNC16(_b + 3 * TILEB + (r1_ * ASTRH + pp) * 2,                         \
               Bl + (size_t)(bnl + r1_) * K + (k0) + pp);                       \
} while (0)

    const int kiters = Khalf / BK;
    LOADCHUNK(0, koff);
    CP_COMMIT();

    for (int i = 0; i < kiters; i++) {
        int s = i & 1;
        CP_WAIT_0();
        __syncthreads();
        if (i + 1 < kiters) {
            LOADCHUNK(s ^ 1, koff + (i + 1) * BK);
            CP_COMMIT();
        }

        uint32_t base = sbu + s * (4 * TILEB);
#pragma unroll
        for (int k16 = 0; k16 < 2; k16++) {
            int koff16 = k16 * 16 + lc * 8;
            uint32_t aH[4][4], aL[4][4], bH[2][4], bL[2][4];
#pragma unroll
            for (int mt = 0; mt < 4; mt++) {
                uint32_t adr = base + ((wm + mt * 16 + lr) * ASTRH + koff16) * 2;
                LDSM4(aH[mt][0], aH[mt][1], aH[mt][2], aH[mt][3], adr);
            }
#pragma unroll
            for (int p = 0; p < 2; p++) {
                uint32_t adr = base + 2 * TILEB + ((wn + p * 16 + lr) * ASTRH + koff16) * 2;
                LDSM4(bH[p][0], bH[p][1], bH[p][2], bH[p][3], adr);
            }
#pragma unroll
            for (int mt = 0; mt < 4; mt++)
#pragma unroll
                for (int nt = 0; nt < 4; nt++) {
                    int p = nt >> 1, w = nt & 1;
                    MMA16816(acc[mt][nt], aH[mt], bH[p][w], bH[p][w + 2]);
                }
            // issue aL + bL loads before term2 so term3 operands arrive early
#pragma unroll
            for (int mt = 0; mt < 4; mt++) {
                uint32_t adr = base + TILEB + ((wm + mt * 16 + lr) * ASTRH + koff16) * 2;
                LDSM4(aL[mt][0], aL[mt][1], aL[mt][2], aL[mt][3], adr);
            }
#pragma unroll
            for (int p = 0; p < 2; p++) {
                uint32_t adr = base + 3 * TILEB + ((wn + p * 16 + lr) * ASTRH + koff16) * 2;
                LDSM4(bL[p][0], bL[p][1], bL[p][2], bL[p][3], adr);
            }
#pragma unroll
            for (int mt = 0; mt < 4; mt++)
#pragma unroll
                for (int nt = 0; nt < 4; nt++) {
                    int p = nt >> 1, w = nt & 1;
                    MMA16816(acc[mt][nt], aH[mt], bL[p][w], bL[p][w + 2]);
                }
#pragma unroll
            for (int mt = 0; mt < 4; mt++)
#pragma unroll
                for (int nt = 0; nt < 4; nt++) {
                    int p = nt >> 1, w = nt & 1;
                    MMA16816(acc[mt][nt], aL[mt], bH[p][w], bH[p][w + 2]);
                }
        }
    }

    int er = lane >> 2, ec = (lane & 3) * 2;
#pragma unroll
    for (int mt = 0; mt < 4; mt++) {
#pragma unroll
        for (int nt = 0; nt < 4; nt++) {
            int r = bm + wm + mt * 16 + er;
            int c = bnl + wn + nt * 8 + ec;
            *(float2*)&C[(size_t)r * Nc + c]       = make_float2(acc[mt][nt][0], acc[mt][nt][1]);
            *(float2*)&C[(size_t)(r + 8) * Nc + c] = make_float2(acc[mt][nt][2], acc[mt][nt][3]);
        }
    }
}

// -------------------- RoPE --------------------
__global__ void rope_table_kernel(const int* __restrict__ start_pos) {
    int idx = blockIdx.x * blockDim.x + threadIdx.x;
    if (idx >= SEQ * 32) return;
    int t = idx >> 5, j = idx & 31;
    const double PI = 3.14159265358979323846;
    double e = (double)(2 * j) / 64.0;
    double invf = pow(500000.0, -e);
    double wavelen = 2.0 * PI / invf;
    double inv;
    if (wavelen > 8192.0) {
        inv = invf / 32.0;
    } else if (wavelen < 2048.0) {
        inv = invf;
    } else {
        double smooth = (8192.0 / wavelen - 1.0) / 3.0;
        inv = (1.0 - smooth) * (invf / 32.0) + smooth * invf;
    }
    float angle = (float)(start_pos[0] + t) * (float)inv;
    g_cos[idx] = (float)cos((double)angle);
    g_sin[idx] = (float)sin((double)angle);
}

// fused partial-add + RoPE + fp16 hi/lo split, q and k in one launch
__global__ void rope_split_qk_kernel(const float* __restrict__ q0, const float* __restrict__ q1,
                                     const float* __restrict__ k0, const float* __restrict__ k1,
                                     __half* __restrict__ qhi, __half* __restrict__ qlo,
                                     __half* __restrict__ khi, __half* __restrict__ klo) {
    int idx = blockIdx.x * blockDim.x + threadIdx.x;
    if (idx >= SEQ * 40 * 32) return;
    int j = idx & 31;
    int hh = (idx >> 5) % 40;
    int t = idx / (32 * 40);
    float c = g_cos[t * 32 + j];
    float s = g_sin[t * 32 + j];
    const float *b0, *b1; __half *hi, *lo; size_t off;
    if (hh < NH) {
        b0 = q0; b1 = q1; hi = qhi; lo = qlo;
        off = (size_t)t * DMODEL + hh * 64 + j;
    } else {
        b0 = k0; b1 = k1; hi = khi; lo = klo;
        off = (size_t)t * KVD + (hh - NH) * 64 + j;
    }
    float x1 = b0[off]      + b1[off];
    float x2 = b0[off + 32] + b1[off + 32];
    float y1 = x1 * c - x2 * s;
    float y2 = x2 * c + x1 * s;
    __half h1 = __float2half_rn(y1), h2 = __float2half_rn(y2);
    hi[off]      = h1;
    hi[off + 32] = h2;
    lo[off]      = __float2half_rn(y1 - __half2float(h1));
    lo[off + 32] = __float2half_rn(y2 - __half2float(h2));
}

// ==================== HMMA flash attention ====================
#define FATR 72
#define FTILE (64 * FATR * 2)
#define FLASH_SMEM (FTILE * 10)

__global__ void __launch_bounds__(128) flash_hmma(
    const __half* __restrict__ qhi, const __half* __restrict__ qlo,
    const __half* __restrict__ khi, const __half* __restrict__ klo,
    const __half* __restrict__ vhi, const __half* __restrict__ vlo,
    __half* __restrict__ chi, __half* __restrict__ clo) {
    extern __shared__ __half fsm[];
    const int h  = blockIdx.x;
    const int qb = gridDim.y - 1 - blockIdx.y;
    const int g  = h >> 2;
    const int tid = threadIdx.x;
    const int wid = tid >> 5, lane = tid & 31;
    const int wm = wid * 16;
    const int er = lane >> 2, ec = (lane & 3) * 2;
    const int lr = lane & 15, lc = lane >> 4;

    uint32_t sb = smem_u32(fsm);
    uint32_t sQh = sb, sQl = sb + FTILE;

#pragma unroll
    for (int l = 0; l < 4; l++) {
        int c = tid + l * 128;
        int row = c >> 3, cc = c & 7;
        size_t off = (size_t)(qb * 64 + row) * DMODEL + h * 64 + cc * 8;
        CP_ASYNC16(sQh + row * FATR * 2 + cc * 16, qhi + off);
        CP_ASYNC16(sQl + row * FATR * 2 + cc * 16, qlo + off);
    }
#define KV_LOAD(kb_, st_) do {                                                  \
    uint32_t base = sb + 2 * FTILE + (st_) * 4 * FTILE;                         \
    _Pragma("unroll")                                                           \
    for (int l = 0; l < 4; l++) {                                               \
        int c = tid + l * 128;                                                  \
        int row = c >> 3, cc = c & 7;                                           \
        size_t off = (size_t)((kb_) * 64 + row) * KVD + g * 64 + cc * 8;        \
        uint32_t d = row * FATR * 2 + cc * 16;                                  \
        CP_ASYNC16(base + 0 * FTILE + d, khi + off);                            \
        CP_ASYNC16(base + 1 * FTILE + d, klo + off);                            \
        CP_ASYNC16(base + 2 * FTILE + d, vhi + off);                            \
        CP_ASYNC16(base + 3 * FTILE + d, vlo + off);                            \
    }                                                                           \
} while (0)

    KV_LOAD(0, 0);
    CP_COMMIT();

    uint32_t aQh[4][4], aQl[4][4];
    float oacc[8][4];
    float mi0 = -INFINITY, mi1 = -INFINITY, li0 = 0.f, li1 = 0.f;
#pragma unroll
    for (int nt = 0; nt < 8; nt++)
#pragma unroll
        for (int j = 0; j < 4; j++) oacc[nt][j] = 0.f;

    for (int kb = 0; kb <= qb; kb++) {
        int stage = kb & 1;
        CP_WAIT_0();
        __syncthreads();
        if (kb < qb) {
            KV_LOAD(kb + 1, stage ^ 1);
            CP_COMMIT();
        }

        if (kb == 0) {
#pragma unroll
            for (int k16 = 0; k16 < 4; k16++) {
                uint32_t ah = sQh + ((wm + lr) * FATR + k16 * 16 + lc * 8) * 2;
                LDSM4(aQh[k16][0], aQh[k16][1], aQh[k16][2], aQh[k16][3], ah);
                uint32_t al = sQl + ((wm + lr) * FATR + k16 * 16 + lc * 8) * 2;
                LDSM4(aQl[k16][0], aQl[k16][1], aQl[k16][2], aQl[k16][3], al);
            }
        }

        uint32_t base = sb + 2 * FTILE + stage * 4 * FTILE;
        uint32_t sKh = base, sKl = base + FTILE;
        uint32_t sVh = base + 2 * FTILE, sVl = base + 3 * FTILE;

        float sacc[8][4];
#pragma unroll
        for (int nt = 0; nt < 8; nt++)
#pragma unroll
            for (int j = 0; j < 4; j++) sacc[nt][j] = 0.f;

#pragma unroll
        for (int k16 = 0; k16 < 4; k16++) {
            uint32_t bh[4][4], bl[4][4];
#pragma unroll
            for (int p = 0; p < 4; p++) {
                uint32_t adr = sKh + ((p * 16 + lr) * FATR + k16 * 16 + lc * 8) * 2;
                LDSM4(bh[p][0], bh[p][1], bh[p][2], bh[p][3], adr);
                adr = sKl + ((p * 16 + lr) * FATR + k16 * 16 + lc * 8) * 2;
                LDSM4(bl[p][0], bl[p][1], bl[p][2], bl[p][3], adr);
            }
#pragma unroll
            for (int nt = 0; nt < 8; nt++) {
                int p = nt >> 1, w = nt & 1;
                MMA16816(sacc[nt], aQh[k16], bh[p][w], bh[p][w + 2]);
                MMA16816(sacc[nt], aQh[k16], bl[p][w], bl[p][w + 2]);
                MMA16816(sacc[nt], aQl[k16], bh[p][w], bh[p][w + 2]);
            }
        }

        if (kb == qb) {
#pragma unroll
            for (int nt = 0; nt < 8; nt++) {
                int c0 = nt * 8 + ec;
                sacc[nt][0] = (c0     <= wm + er)     ? sacc[nt][0] * 0.125f : -INFINITY;
                sacc[nt][1] = (c0 + 1 <= wm + er)     ? sacc[nt][1] * 0.125f : -INFINITY;
                sacc[nt][2] = (c0     <= wm + er + 8) ? sacc[nt][2] * 0.125f : -INFINITY;
                sacc[nt][3] = (c0 + 1 <= wm + er + 8) ? sacc[nt][3] * 0.125f : -INFINITY;
            }
        } else {
#pragma unroll
            for (int nt = 0; nt < 8; nt++)
#pragma unroll
                for (int j = 0; j < 4; j++) sacc[nt][j] *= 0.125f;
        }

        float mx0 = -INFINITY, mx1 = -INFINITY;
#pragma unroll
        for (int nt = 0; nt < 8; nt++) {
            mx0 = fmaxf(mx0, fmaxf(sacc[nt][0], sacc[nt][1]));
            mx1 = fmaxf(mx1, fmaxf(sacc[nt][2], sacc[nt][3]));
        }
#pragma unroll
        for (int off = 1; off < 4; off <<= 1) {
            mx0 = fmaxf(mx0, __shfl_xor_sync(0xffffffffu, mx0, off));
            mx1 = fmaxf(mx1, __shfl_xor_sync(0xffffffffu, mx1, off));
        }
        float mn0 = fmaxf(mi0, mx0), mn1 = fmaxf(mi1, mx1);
        float sum0 = 0.f, sum1 = 0.f;
#pragma unroll
        for (int nt = 0; nt < 8; nt++) {
            sacc[nt][0] = __expf(sacc[nt][0] - mn0);
            sacc[nt][1] = __expf(sacc[nt][1] - mn0);
            sacc[nt][2] = __expf(sacc[nt][2] - mn1);
            sacc[nt][3] = __expf(sacc[nt][3] - mn1);
            sum0 += sacc[nt][0] + sacc[nt][1];
            sum1 += sacc[nt][2] + sacc[nt][3];
        }
#pragma unroll
        for (int off = 1; off < 4; off <<= 1) {
            sum0 += __shfl_xor_sync(0xffffffffu, sum0, off);
            sum1 += __shfl_xor_sync(0xffffffffu, sum1, off);
        }
        float sc0 = __expf(mi0 - mn0), sc1 = __expf(mi1 - mn1);
        li0 = li0 * sc0 + sum0; li1 = li1 * sc1 + sum1;
        mi0 = mn0; mi1 = mn1;
#pragma unroll
        for (int nt = 0; nt < 8; nt++) {
            oacc[nt][0] *= sc0; oacc[nt][1] *= sc0;
            oacc[nt][2] *= sc1; oacc[nt][3] *= sc1;
        }

#pragma unroll
        for (int k16 = 0; k16 < 4; k16++) {
            uint32_t ph[4], pl[4];
#pragma unroll
            for (int half16 = 0; half16 < 2; half16++) {
                int st = 2 * k16 + half16;
                __half2 h01 = __floats2half2_rn(sacc[st][0], sacc[st][1]);
                float2 f01 = __half22float2(h01);
                __half2 l01 = __floats2half2_rn(sacc[st][0] - f01.x, sacc[st][1] - f01.y);
                __half2 h23 = __floats2half2_rn(sacc[st][2], sacc[st][3]);
                float2 f23 = __half22float2(h23);
                __half2 l23 = __floats2half2_rn(sacc[st][2] - f23.x, sacc[st][3] - f23.y);
                ph[half16 * 2]     = *(uint32_t*)&h01;
                ph[half16 * 2 + 1] = *(uint32_t*)&h23;
                pl[half16 * 2]     = *(uint32_t*)&l01;
                pl[half16 * 2 + 1] = *(uint32_t*)&l23;
            }
            uint32_t bvh[4][4], bvl[4][4];
#pragma unroll
            for (int p = 0; p < 4; p++) {
                uint32_t adr = sVh + ((k16 * 16 + lr) * FATR + p * 16 + lc * 8) * 2;
                LDSM4T(bvh[p][0], bvh[p][1], bvh[p][2], bvh[p][3], adr);
                adr = sVl + ((k16 * 16 + lr) * FATR + p * 16 + lc * 8) * 2;
                LDSM4T(bvl[p][0], bvl[p][1], bvl[p][2], bvl[p][3], adr);
            }
#pragma unroll
            for (int nt = 0; nt < 8; nt++) {
                int p = nt >> 1, w = (nt & 1) * 2;
                MMA16816(oacc[nt], ph, bvh[p][w], bvh[p][w + 1]);
                MMA16816(oacc[nt], ph, bvl[p][w], bvl[p][w + 1]);
                MMA16816(oacc[nt], pl, bvh[p][w], bvh[p][w + 1]);
            }
        }
    }

    float inv0 = 1.0f / li0, inv1 = 1.0f / li1;
    int r0g = qb * 64 + wm + er, r1g = r0g + 8;
#pragma unroll
    for (int nt = 0; nt < 8; nt++) {
        int c = h * 64 + nt * 8 + ec;
        float v0 = oacc[nt][0] * inv0, v1 = oacc[nt][1] * inv0;
        float v2 = oacc[nt][2] * inv1, v3 = oacc[nt][3] * inv1;
        __half2 h0 = __floats2half2_rn(v0, v1);
        float2 f0 = __half22float2(h0);
        __half2 l0 = __floats2half2_rn(v0 - f0.x, v1 - f0.y);
        __half2 h1 = __floats2half2_rn(v2, v3);
        float2 f1 = __half22float2(h1);
        __half2 l1 = __floats2half2_rn(v2 - f1.x, v3 - f1.y);
        *(__half2*)&chi[(size_t)r0g * DMODEL + c] = h0;
        *(__half2*)&clo[(size_t)r0g * DMODEL + c] = l0;
        *(__half2*)&chi[(size_t)r1g * DMODEL + c] = h1;
        *(__half2*)&clo[(size_t)r1g * DMODEL + c] = l1;
    }
}

// -------------------- launch --------------------
extern "C" void kernel_launch(void* const* d_in, const int* in_sizes, int n_in,
                              void* d_out, int out_size) {
    const float* x  = (const float*)d_in[0];
    const float* Wq = (const float*)d_in[1];
    const float* Wk = (const float*)d_in[2];
    const float* Wv = (const float*)d_in[3];
    const float* Wo = (const float*)d_in[4];
    const int* start_pos = (const int*)d_in[5];
    float* out = (float*)d_out;

    float *qp, *kp, *vp, *qp2, *kp2, *vp2;
    cudaGetSymbolAddress((void**)&qp, g_q);   cudaGetSymbolAddress((void**)&qp2, g_q2);
    cudaGetSymbolAddress((void**)&kp, g_k);   cudaGetSymbolAddress((void**)&kp2, g_k2);
    cudaGetSymbolAddress((void**)&vp, g_v);   cudaGetSymbolAddress((void**)&vp2, g_v2);
    __half *xhi, *xlo, *wqhi, *wqlo, *wkhi, *wklo, *wvhi, *wvlo, *wohi, *wolo;
    __half *chi, *clo, *qh, *ql, *kh, *kl, *vh, *vl;
    cudaGetSymbolAddress((void**)&xhi, g_xhi);   cudaGetSymbolAddress((void**)&xlo, g_xlo);
    cudaGetSymbolAddress((void**)&wqhi, g_wqhi); cudaGetSymbolAddress((void**)&wqlo, g_wqlo);
    cudaGetSymbolAddress((void**)&wkhi, g_wkhi); cudaGetSymbolAddress((void**)&wklo, g_wklo);
    cudaGetSymbolAddress((void**)&wvhi, g_wvhi); cudaGetSymbolAddress((void**)&wvlo, g_wvlo);
    cudaGetSymbolAddress((void**)&wohi, g_wohi); cudaGetSymbolAddress((void**)&wolo, g_wolo);
    cudaGetSymbolAddress((void**)&chi, g_chi);   cudaGetSymbolAddress((void**)&clo, g_clo);
    cudaGetSymbolAddress((void**)&qh, g_qh);     cudaGetSymbolAddress((void**)&ql, g_ql);
    cudaGetSymbolAddress((void**)&kh, g_kh);     cudaGetSymbolAddress((void**)&kl, g_kl);
    cudaGetSymbolAddress((void**)&vh, g_vh);     cudaGetSymbolAddress((void**)&vl, g_vl);

    cudaFuncSetAttribute(gemm3, cudaFuncAttributeMaxDynamicSharedMemorySize, GSMEM);
    cudaFuncSetAttribute(flash_hmma, cudaFuncAttributeMaxDynamicSharedMemorySize,
                         FLASH_SMEM);

    split_w_kernel<<<(2*WQ4 + 2*WK4) / 256, 256>>>(Wq, Wk, Wv, Wo,
        wqhi, wqlo, wkhi, wklo, wvhi, wvlo, wohi, wolo);
    split_kernel<<<(SEQ*DMODEL/4) / 256, 256>>>(x, xhi, xlo, SEQ*DMODEL/4);
    rope_table_kernel<<<(SEQ * 32 + 255) / 256, 256>>>(start_pos);
    // fused Q/K/V projection, split-K=2 (z dim), partials to qp/qp2 etc.
    gemm3<<<dim3(24, SEQ/128, 2), 256, GSMEM>>>(
        xhi, xlo,
        wqhi, wqlo, qp, qp2, DMODEL, 16,
        wkhi, wklo, kp, kp2, KVD, 4,
        wvhi, wvlo, vp, vp2, KVD,
        DMODEL, DMODEL/2);
    rope_split_qk_kernel<<<(SEQ * 40 * 32) / 256, 256>>>(qp, qp2, kp, kp2, qh, ql, kh, kl);
    split_add_kernel<<<(SEQ*KVD/4) / 256, 256>>>(vp, vp2, vh, vl, SEQ*KVD/4);
    flash_hmma<<<dim3(NH, SEQ / 64), 128, FLASH_SMEM>>>(qh, ql, kh, kl, vh, vl, chi, clo);
    // O projection: single wave already (256 CTAs), no split-K
    gemm3<<<dim3(16, SEQ/128, 1), 256, GSMEM>>>(
        chi, clo,
        wohi, wolo, out, out, DMODEL, 16,
        wohi, wolo, out, out, DMODEL, 0,
        wohi, wolo, out, out, DMODEL,
        DMODEL, DMODEL);
}